// round 10
// baseline (speedup 1.0000x reference)
#include <cuda_runtime.h>
#include <math.h>
#include <stdint.h>

// ---------------------------------------------------------------------------
// Static device scratch (no allocations allowed anywhere).
// ---------------------------------------------------------------------------
#define NMAX 65536
#define EMAX 2200000

__device__ float g_h1[(size_t)NMAX * 256];
__device__ float g_x2[(size_t)NMAX * 256];
__device__ float g_h2[(size_t)NMAX * 64];
__device__ float g_as1[NMAX * 4];
__device__ float g_ad1[NMAX * 4];
__device__ float g_as2[NMAX];
__device__ float g_ad2[NMAX];
__device__ int   g_deg[NMAX];
__device__ int   g_pos[NMAX];
__device__ int   g_rowptr[NMAX + 1];
__device__ int   g_esrc[EMAX];

// ---------------------------------------------------------------------------
// CSR construction (counting sort by destination). edge_index is INT32.
// ---------------------------------------------------------------------------
__global__ void zero_deg_kernel(int Nn) {
    int i = blockIdx.x * blockDim.x + threadIdx.x;
    if (i < Nn) g_deg[i] = 0;
}

__global__ void count_kernel(const int* __restrict__ ei, int E, int Nn) {
    int i = blockIdx.x * blockDim.x + threadIdx.x;
    int tot = E + Nn;
    if (i >= tot) return;
    int d = (i < E) ? ei[E + i] : (i - E);
    if ((unsigned)d < (unsigned)Nn) atomicAdd(&g_deg[d], 1);
}

__global__ void scan_kernel(int N) {
    __shared__ int ssum[1024];
    int tid = threadIdx.x;
    int chunk = (N + 1023) >> 10;
    int start = tid * chunk;
    int end = min(start + chunk, N);
    int s = 0;
    for (int i = start; i < end; i++) s += g_deg[i];
    ssum[tid] = s;
    __syncthreads();
    for (int off = 1; off < 1024; off <<= 1) {
        int v = (tid >= off) ? ssum[tid - off] : 0;
        __syncthreads();
        ssum[tid] += v;
        __syncthreads();
    }
    int run = (tid > 0) ? ssum[tid - 1] : 0;
    for (int i = start; i < end; i++) {
        g_rowptr[i] = run;
        g_pos[i] = run;
        run += g_deg[i];
    }
    if (start < N && end == N) g_rowptr[N] = run;
}

__global__ void fill_kernel(const int* __restrict__ ei, int E, int Nn) {
    int i = blockIdx.x * blockDim.x + threadIdx.x;
    int tot = E + Nn;
    if (i >= tot) return;
    int s, d;
    if (i < E) { s = ei[i]; d = ei[E + i]; }
    else       { s = d = i - E; }
    if ((unsigned)d >= (unsigned)Nn || (unsigned)s >= (unsigned)Nn) return;
    int slot = atomicAdd(&g_pos[d], 1);
    g_esrc[slot] = s;
}

// ---------------------------------------------------------------------------
// TF32 tensor-core GEMM, 3-term split (x = hi+lo; x*y ~= hi*hi + hi*lo + lo*hi)
// for fp32-grade accuracy. Fragment-major shared layout so each thread loads
// its m16n8k8 fragment with ONE LDS.128 (A) / LDS.64 (B):
//   element (r,k) of A -> [k/8][r/16][lane=(r%8)*4+(k%4)][idx=(r%16)/8 + 2*((k%8)/4)]
//   element (k,c) of B -> [k/8][c/8 ][lane=(c%8)*4+(k%4)][idx=(k%8)/4]
// This mapping reproduces exactly the fragment order validated in round 9.
// C[M,N] = A[M,K] @ B[K,N], row-major. 256 threads = 8 warps (4x2 warp grid).
// ---------------------------------------------------------------------------
__device__ __forceinline__ float f2tf32(float x) {
    uint32_t u;
    asm("cvt.rna.tf32.f32 %0, %1;" : "=r"(u) : "f"(x));
    return __uint_as_float(u);
}

__device__ __forceinline__ void mma_tf32(float c[4], const uint32_t a[4],
                                         const uint32_t b[2]) {
    asm volatile(
        "mma.sync.aligned.m16n8k8.row.col.f32.tf32.tf32.f32 "
        "{%0,%1,%2,%3}, {%4,%5,%6,%7}, {%8,%9}, {%0,%1,%2,%3};\n"
        : "+f"(c[0]), "+f"(c[1]), "+f"(c[2]), "+f"(c[3])
        : "r"(a[0]), "r"(a[1]), "r"(a[2]), "r"(a[3]), "r"(b[0]), "r"(b[1]));
}

template <int BM, int BN, int WM, int WN>
__device__ __forceinline__ void mma_gemm_body(const float* __restrict__ A,
                                              const float* __restrict__ B,
                                              float* __restrict__ C,
                                              int M, int N, int K) {
    constexpr int BK = 16;
    constexpr int THREADS = 256;
    constexpr int SL = BK / 8;                    // 8-k slices per tile
    constexpr int MB = BM / 16;
    constexpr int NB = BN / 8;
    constexpr int MT = WM / 16;
    constexpr int NT = WN / 8;
    constexpr int A_F4 = BM * BK / 4 / THREADS;
    constexpr int B_F4 = BK * BN / 4 / THREADS;

    __shared__ float Ah2[SL][MB][32][4], Al2[SL][MB][32][4];
    __shared__ float Bh2[SL][NB][32][2], Bl2[SL][NB][32][2];

    const int tid    = threadIdx.x;
    const int warpId = tid >> 5;
    const int lane   = tid & 31;
    const int g = lane >> 2;
    const int t = lane & 3;

    const int row0 = blockIdx.y * BM;
    const int col0 = blockIdx.x * BN;
    const int wm0  = (warpId & 3) * WM;
    const int wn0  = (warpId >> 2) * WN;
    const int wmb  = wm0 >> 4;                    // warp m-block base
    const int wnb  = wn0 >> 3;                    // warp n-block base

    float4 aReg[A_F4], bReg[B_F4];

    auto fetch = [&](int k0) {
#pragma unroll
        for (int q = 0; q < A_F4; q++) {
            int i = tid + q * THREADS;
            int r = i / (BK / 4);
            int c = (i % (BK / 4)) * 4;
            aReg[q] = make_float4(0.f, 0.f, 0.f, 0.f);
            if (row0 + r < M)
                aReg[q] = *reinterpret_cast<const float4*>(
                    A + (size_t)(row0 + r) * K + k0 + c);
        }
#pragma unroll
        for (int q = 0; q < B_F4; q++) {
            int i = tid + q * THREADS;
            int r = i / (BN / 4);
            int c = (i % (BN / 4)) * 4;
            bReg[q] = *reinterpret_cast<const float4*>(
                B + (size_t)(k0 + r) * N + col0 + c);
        }
    };
    auto stage = [&]() {
#pragma unroll
        for (int q = 0; q < A_F4; q++) {
            int i  = tid + q * THREADS;
            int r  = i / (BK / 4);
            int c4 = (i % (BK / 4)) * 4;
            float v[4] = {aReg[q].x, aReg[q].y, aReg[q].z, aReg[q].w};
#pragma unroll
            for (int e = 0; e < 4; e++) {
                int k  = c4 + e;
                int sl = k >> 3;
                int ln = ((r & 7) << 2) + (k & 3);
                int ix = ((r & 15) >> 3) + (((k & 7) >> 2) << 1);
                float hi = f2tf32(v[e]);
                Ah2[sl][r >> 4][ln][ix] = hi;
                Al2[sl][r >> 4][ln][ix] = f2tf32(v[e] - hi);
            }
        }
#pragma unroll
        for (int q = 0; q < B_F4; q++) {
            int i  = tid + q * THREADS;
            int k  = i / (BN / 4);
            int c0 = (i % (BN / 4)) * 4;
            int sl = k >> 3;
            int ix = (k & 7) >> 2;
            float v[4] = {bReg[q].x, bReg[q].y, bReg[q].z, bReg[q].w};
#pragma unroll
            for (int e = 0; e < 4; e++) {
                int c  = c0 + e;
                int ln = ((c & 7) << 2) + (k & 3);
                float hi = f2tf32(v[e]);
                Bh2[sl][c >> 3][ln][ix] = hi;
                Bl2[sl][c >> 3][ln][ix] = f2tf32(v[e] - hi);
            }
        }
    };

    float acc[MT][NT][4];
#pragma unroll
    for (int mt = 0; mt < MT; mt++)
#pragma unroll
        for (int nt = 0; nt < NT; nt++)
#pragma unroll
            for (int e = 0; e < 4; e++) acc[mt][nt][e] = 0.f;

    fetch(0);
    stage();
    __syncthreads();

    for (int k0 = 0; k0 < K; k0 += BK) {
        if (k0 + BK < K) fetch(k0 + BK);     // prefetch next tile into registers

#pragma unroll
        for (int sl = 0; sl < SL; sl++) {
            uint32_t ah[MT][4], al[MT][4];
#pragma unroll
            for (int mt = 0; mt < MT; mt++) {
                float4 vh = *reinterpret_cast<const float4*>(&Ah2[sl][wmb + mt][lane][0]);
                float4 vl = *reinterpret_cast<const float4*>(&Al2[sl][wmb + mt][lane][0]);
                ah[mt][0] = __float_as_uint(vh.x); ah[mt][1] = __float_as_uint(vh.y);
                ah[mt][2] = __float_as_uint(vh.z); ah[mt][3] = __float_as_uint(vh.w);
                al[mt][0] = __float_as_uint(vl.x); al[mt][1] = __float_as_uint(vl.y);
                al[mt][2] = __float_as_uint(vl.z); al[mt][3] = __float_as_uint(vl.w);
            }
            uint32_t bh[NT][2], bl[NT][2];
#pragma unroll
            for (int nt = 0; nt < NT; nt++) {
                float2 vh = *reinterpret_cast<const float2*>(&Bh2[sl][wnb + nt][lane][0]);
                float2 vl = *reinterpret_cast<const float2*>(&Bl2[sl][wnb + nt][lane][0]);
                bh[nt][0] = __float_as_uint(vh.x); bh[nt][1] = __float_as_uint(vh.y);
                bl[nt][0] = __float_as_uint(vl.x); bl[nt][1] = __float_as_uint(vl.y);
            }
#pragma unroll
            for (int mt = 0; mt < MT; mt++)
#pragma unroll
                for (int nt = 0; nt < NT; nt++) {
                    mma_tf32(acc[mt][nt], ah[mt], bh[nt]);   // hi*hi
                    mma_tf32(acc[mt][nt], ah[mt], bl[nt]);   // hi*lo
                    mma_tf32(acc[mt][nt], al[mt], bh[nt]);   // lo*hi
                }
        }
        __syncthreads();
        if (k0 + BK < K) {
            stage();
            __syncthreads();
        }
    }

    // ---- epilogue: c0/c1 at (r, c..c+1), c2/c3 at (r+8, c..c+1) ----
#pragma unroll
    for (int mt = 0; mt < MT; mt++)
#pragma unroll
        for (int nt = 0; nt < NT; nt++) {
            int r = row0 + wm0 + mt * 16 + g;
            int c = col0 + wn0 + nt * 8 + 2 * t;
            if (r < M)
                *reinterpret_cast<float2*>(C + (size_t)r * N + c) =
                    make_float2(acc[mt][nt][0], acc[mt][nt][1]);
            if (r + 8 < M)
                *reinterpret_cast<float2*>(C + (size_t)(r + 8) * N + c) =
                    make_float2(acc[mt][nt][2], acc[mt][nt][3]);
        }
}

__global__ void __launch_bounds__(256)
sgemm1_kernel(const float* __restrict__ A, const float* __restrict__ B,
              int M, int N, int K) {
    mma_gemm_body<128, 128, 32, 64>(A, B, g_h1, M, N, K);
}

__global__ void __launch_bounds__(256)
sgemm2_kernel(const float* __restrict__ B, int M, int N, int K) {
    mma_gemm_body<128, 64, 32, 32>(g_x2, B, g_h2, M, N, K);
}

// ---------------------------------------------------------------------------
// alpha_s[n,h] = <h[n,h,:], a_src[h,:]>,  alpha_d likewise.  One warp / node.
// ---------------------------------------------------------------------------
template <int H, int C>
__device__ __forceinline__ void alpha_body(const float* __restrict__ hfeat,
                                           const float* __restrict__ a_src,
                                           const float* __restrict__ a_dst,
                                           float* __restrict__ as_out,
                                           float* __restrict__ ad_out, int Nn) {
    constexpr int HC  = H * C;
    constexpr int CPL = HC / 32;
    constexpr int LPH = 32 / H;
    int warp = (blockIdx.x * blockDim.x + threadIdx.x) >> 5;
    int lane = threadIdx.x & 31;
    if (warp >= Nn) return;

    const float* hp = hfeat + (size_t)warp * HC + lane * CPL;
    float ss = 0.f, sd = 0.f;
#pragma unroll
    for (int k = 0; k < CPL; k++) {
        float v = hp[k];
        ss = fmaf(v, a_src[lane * CPL + k], ss);
        sd = fmaf(v, a_dst[lane * CPL + k], sd);
    }
#pragma unroll
    for (int o = LPH / 2; o > 0; o >>= 1) {
        ss += __shfl_xor_sync(0xFFFFFFFFu, ss, o);
        sd += __shfl_xor_sync(0xFFFFFFFFu, sd, o);
    }
    if ((lane % LPH) == 0) {
        int head = lane / LPH;
        as_out[warp * H + head] = ss;
        ad_out[warp * H + head] = sd;
    }
}

__global__ void alpha1_kernel(const float* __restrict__ a_src,
                              const float* __restrict__ a_dst, int Nn) {
    alpha_body<4, 64>(g_h1, a_src, a_dst, g_as1, g_ad1, Nn);
}

__global__ void alpha2_kernel(const float* __restrict__ a_src,
                              const float* __restrict__ a_dst, int Nn) {
    alpha_body<1, 64>(g_h2, a_src, a_dst, g_as2, g_ad2, Nn);
}

// ---------------------------------------------------------------------------
// Per-node edge softmax + weighted aggregation.  One warp per destination.
// Max-free softmax (e is bounded; overflow-safe, mathematically identical).
// ---------------------------------------------------------------------------
template <int H, int C, bool RELU>
__device__ __forceinline__ void aggregate_body(const float* __restrict__ hfeat,
                                               const float* __restrict__ as_in,
                                               const float* __restrict__ ad_in,
                                               const float* __restrict__ bias,
                                               float* __restrict__ out, int Nn) {
    constexpr int HC  = H * C;
    constexpr int CPL = HC / 32;
    int warp = (blockIdx.x * blockDim.x + threadIdx.x) >> 5;
    int lane = threadIdx.x & 31;
    if (warp >= Nn) return;
    const int n   = warp;
    const int beg = g_rowptr[n];
    const int end = g_rowptr[n + 1];

    float adv[H];
#pragma unroll
    for (int h = 0; h < H; h++) adv[h] = ad_in[n * H + h];

    float sm[H];
#pragma unroll
    for (int h = 0; h < H; h++) sm[h] = 0.f;
    for (int j = beg + lane; j < end; j += 32) {
        int s = g_esrc[j];
        if constexpr (H == 4) {
            float4 av = *reinterpret_cast<const float4*>(as_in + s * 4);
            float ev[4] = {av.x, av.y, av.z, av.w};
#pragma unroll
            for (int h = 0; h < 4; h++) {
                float e = ev[h] + adv[h];
                e = (e > 0.f) ? e : 0.2f * e;
                sm[h] += expf(e);
            }
        } else {
            float e = as_in[s] + adv[0];
            e = (e > 0.f) ? e : 0.2f * e;
            sm[0] += expf(e);
        }
    }
#pragma unroll
    for (int h = 0; h < H; h++) {
#pragma unroll
        for (int o = 16; o > 0; o >>= 1)
            sm[h] += __shfl_xor_sync(0xFFFFFFFFu, sm[h], o);
        sm[h] = 1.0f / (sm[h] + 1e-16f);
    }

    const int chan0 = lane * CPL;
    const int headL = chan0 / C;
    const float adh  = adv[headL];
    const float ismh = sm[headL];

    auto edge_alpha = [&](int s) -> float {
        float e = as_in[s * H + headL] + adh;
        e = (e > 0.f) ? e : 0.2f * e;
        return expf(e) * ismh;
    };

    float acc[CPL];
#pragma unroll
    for (int k = 0; k < CPL; k++) acc[k] = 0.f;

    int j = beg;
    for (; j + 3 < end; j += 4) {
        int   s[4];
        float a[4];
#pragma unroll
        for (int q = 0; q < 4; q++) s[q] = g_esrc[j + q];
#pragma unroll
        for (int q = 0; q < 4; q++) a[q] = edge_alpha(s[q]);
        if constexpr (CPL == 8) {
            float4 va[4], vb[4];
#pragma unroll
            for (int q = 0; q < 4; q++) {
                const float* p = hfeat + (size_t)s[q] * HC + chan0;
                va[q] = *reinterpret_cast<const float4*>(p);
                vb[q] = *reinterpret_cast<const float4*>(p + 4);
            }
#pragma unroll
            for (int q = 0; q < 4; q++) {
                acc[0] = fmaf(va[q].x, a[q], acc[0]);
                acc[1] = fmaf(va[q].y, a[q], acc[1]);
                acc[2] = fmaf(va[q].z, a[q], acc[2]);
                acc[3] = fmaf(va[q].w, a[q], acc[3]);
                acc[4] = fmaf(vb[q].x, a[q], acc[4]);
                acc[5] = fmaf(vb[q].y, a[q], acc[5]);
                acc[6] = fmaf(vb[q].z, a[q], acc[6]);
                acc[7] = fmaf(vb[q].w, a[q], acc[7]);
            }
        } else {
            float2 v[4];
#pragma unroll
            for (int q = 0; q < 4; q++)
                v[q] = *reinterpret_cast<const float2*>(hfeat + (size_t)s[q] * HC + chan0);
#pragma unroll
            for (int q = 0; q < 4; q++) {
                acc[0] = fmaf(v[q].x, a[q], acc[0]);
                acc[1] = fmaf(v[q].y, a[q], acc[1]);
            }
        }
    }
    for (; j < end; j++) {
        int s0 = g_esrc[j];
        float a0 = edge_alpha(s0);
        const float* p0 = hfeat + (size_t)s0 * HC + chan0;
        if constexpr (CPL == 8) {
            float4 v0a = *reinterpret_cast<const float4*>(p0);
            float4 v0b = *reinterpret_cast<const float4*>(p0 + 4);
            acc[0] = fmaf(v0a.x, a0, acc[0]); acc[1] = fmaf(v0a.y, a0, acc[1]);
            acc[2] = fmaf(v0a.z, a0, acc[2]); acc[3] = fmaf(v0a.w, a0, acc[3]);
            acc[4] = fmaf(v0b.x, a0, acc[4]); acc[5] = fmaf(v0b.y, a0, acc[5]);
            acc[6] = fmaf(v0b.z, a0, acc[6]); acc[7] = fmaf(v0b.w, a0, acc[7]);
        } else {
            float2 v0 = *reinterpret_cast<const float2*>(p0);
            acc[0] = fmaf(v0.x, a0, acc[0]); acc[1] = fmaf(v0.y, a0, acc[1]);
        }
    }

    float* op = out + (size_t)n * HC + chan0;
#pragma unroll
    for (int k = 0; k < CPL; k++) {
        float v = acc[k] + bias[chan0 + k];
        if constexpr (RELU) v = fmaxf(v, 0.f);
        op[k] = v;
    }
}

__global__ void agg1_kernel(const float* __restrict__ bias, int Nn) {
    aggregate_body<4, 64, true>(g_h1, g_as1, g_ad1, bias, g_x2, Nn);
}

__global__ void agg2_kernel(const float* __restrict__ bias,
                            float* __restrict__ out, int Nn) {
    aggregate_body<1, 64, false>(g_h2, g_as2, g_ad2, bias, out, Nn);
}

// ---------------------------------------------------------------------------
// kernel_launch — pure kernel launches, no runtime API calls.
// ---------------------------------------------------------------------------
extern "C" void kernel_launch(void* const* d_in, const int* in_sizes, int n_in,
                              void* d_out, int out_size) {
    const float* x      = (const float*)d_in[0];
    const int*   ei     = (const int*)d_in[1];
    const float* W1     = (const float*)d_in[2];
    const float* a_src1 = (const float*)d_in[3];
    const float* a_dst1 = (const float*)d_in[4];
    const float* b1     = (const float*)d_in[5];
    const float* W2     = (const float*)d_in[6];
    const float* a_src2 = (const float*)d_in[7];
    const float* a_dst2 = (const float*)d_in[8];
    const float* b2     = (const float*)d_in[9];

    const int C   = in_sizes[9];            // 64
    const int H   = in_sizes[3] / C;        // 4
    const int HC1 = H * C;                  // 256
    const int Fin = in_sizes[2] / HC1;      // 128
    const int Nn  = in_sizes[0] / Fin;      // 50000
    const int E   = in_sizes[1] / 2;        // 800000
    const int Etot = E + Nn;

    if (Nn > NMAX || Etot > EMAX || H != 4 || C != 64) return;

    zero_deg_kernel<<<(Nn + 255) / 256, 256>>>(Nn);
    count_kernel<<<(Etot + 255) / 256, 256>>>(ei, E, Nn);
    scan_kernel<<<1, 1024>>>(Nn);
    fill_kernel<<<(Etot + 255) / 256, 256>>>(ei, E, Nn);

    const int warpBlocks = (Nn + 7) / 8;

    {
        dim3 grid(HC1 / 128, (Nn + 127) / 128);
        sgemm1_kernel<<<grid, 256>>>(x, W1, Nn, HC1, Fin);
    }
    alpha1_kernel<<<warpBlocks, 256>>>(a_src1, a_dst1, Nn);
    agg1_kernel<<<warpBlocks, 256>>>(b1, Nn);

    {
        dim3 grid(C / 64, (Nn + 127) / 128);
        sgemm2_kernel<<<grid, 256>>>(W2, Nn, C, HC1);
    }
    alpha2_kernel<<<warpBlocks, 256>>>(a_src2, a_dst2, Nn);
    agg2_kernel<<<warpBlocks, 256>>>(b2, (float*)d_out, Nn);
}

// round 11
// speedup vs baseline: 1.3916x; 1.3916x over previous
#include <cuda_runtime.h>
#include <math.h>
#include <stdint.h>

// ---------------------------------------------------------------------------
// Static device scratch (no allocations allowed anywhere).
// Sized for N <= 65536 nodes, E_total <= 2.2M edges (instance: 50000 / 850000).
// ---------------------------------------------------------------------------
#define NMAX 65536
#define EMAX 2200000

__device__ float g_h1[(size_t)NMAX * 256];   // layer-1 features  h1 = x @ W1
__device__ float g_x2[(size_t)NMAX * 256];   // relu(agg1 + b1) = layer-2 input
__device__ float g_h2[(size_t)NMAX * 64];    // layer-2 features  h2 = x2 @ W2
__device__ float g_as1[NMAX * 4];
__device__ float g_ad1[NMAX * 4];
__device__ float g_as2[NMAX];
__device__ float g_ad2[NMAX];
__device__ int   g_deg[NMAX];
__device__ int   g_pos[NMAX];
__device__ int   g_rowptr[NMAX + 1];
__device__ int   g_esrc[EMAX];               // src node of each dst-sorted edge

// ---------------------------------------------------------------------------
// CSR construction (counting sort by destination). edge_index is INT32.
// ---------------------------------------------------------------------------
__global__ void zero_deg_kernel(int Nn) {
    int i = blockIdx.x * blockDim.x + threadIdx.x;
    if (i < Nn) g_deg[i] = 0;
}

__global__ void count_kernel(const int* __restrict__ ei, int E, int Nn) {
    int i = blockIdx.x * blockDim.x + threadIdx.x;
    int tot = E + Nn;
    if (i >= tot) return;
    int d = (i < E) ? ei[E + i] : (i - E);
    if ((unsigned)d < (unsigned)Nn) atomicAdd(&g_deg[d], 1);
}

__global__ void scan_kernel(int N) {
    __shared__ int ssum[1024];
    int tid = threadIdx.x;
    int chunk = (N + 1023) >> 10;
    int start = tid * chunk;
    int end = min(start + chunk, N);
    int s = 0;
    for (int i = start; i < end; i++) s += g_deg[i];
    ssum[tid] = s;
    __syncthreads();
    for (int off = 1; off < 1024; off <<= 1) {
        int v = (tid >= off) ? ssum[tid - off] : 0;
        __syncthreads();
        ssum[tid] += v;
        __syncthreads();
    }
    int run = (tid > 0) ? ssum[tid - 1] : 0;
    for (int i = start; i < end; i++) {
        g_rowptr[i] = run;
        g_pos[i] = run;
        run += g_deg[i];
    }
    if (start < N && end == N) g_rowptr[N] = run;
}

__global__ void fill_kernel(const int* __restrict__ ei, int E, int Nn) {
    int i = blockIdx.x * blockDim.x + threadIdx.x;
    int tot = E + Nn;
    if (i >= tot) return;
    int s, d;
    if (i < E) { s = ei[i]; d = ei[E + i]; }
    else       { s = d = i - E; }
    if ((unsigned)d >= (unsigned)Nn || (unsigned)s >= (unsigned)Nn) return;
    int slot = atomicAdd(&g_pos[d], 1);
    g_esrc[slot] = s;
}

// ---------------------------------------------------------------------------
// Double-buffered fp32 SGEMM: C[M,N] = A[M,K] @ B[K,N]  (row-major)
// 256 threads, BK=16, register-staged global prefetch overlaps the next
// tile's loads with the current tile's 1024 FMAs/thread. One sync / k-tile.
// (Proven fastest variant: round 8, 427 us total.)
// ---------------------------------------------------------------------------
template <int BM, int BN, int BK, int TM, int TN>
__device__ __forceinline__ void sgemm_body(const float* __restrict__ A,
                                           const float* __restrict__ B,
                                           float* __restrict__ C,
                                           int M, int N, int K) {
    constexpr int THREADS = (BM / TM) * (BN / TN);   // 256
    constexpr int A_LD = BM * BK / (4 * THREADS);    // float4 loads per thread
    constexpr int B_LD = BK * BN / (4 * THREADS);
    constexpr int TXN = BN / TN;                     // threads along N

    __shared__ float As[2][BK][BM];
    __shared__ float Bs[2][BK][BN];

    const int tid  = threadIdx.x;
    const int row0 = blockIdx.y * BM;
    const int col0 = blockIdx.x * BN;
    const int tx = tid % TXN;
    const int ty = tid / TXN;

    float4 aReg[A_LD], bReg[B_LD];

    auto fetch = [&](int k0) {
#pragma unroll
        for (int q = 0; q < A_LD; q++) {
            int i  = tid + q * THREADS;
            int r  = i / (BK / 4);
            int c4 = (i % (BK / 4)) * 4;
            aReg[q] = make_float4(0.f, 0.f, 0.f, 0.f);
            if (row0 + r < M)
                aReg[q] = *reinterpret_cast<const float4*>(
                    A + (size_t)(row0 + r) * K + k0 + c4);
        }
#pragma unroll
        for (int q = 0; q < B_LD; q++) {
            int i = tid + q * THREADS;
            int r = i / (BN / 4);
            int c = (i % (BN / 4)) * 4;
            bReg[q] = *reinterpret_cast<const float4*>(
                B + (size_t)(k0 + r) * N + col0 + c);
        }
    };
    auto stage = [&](int buf) {
#pragma unroll
        for (int q = 0; q < A_LD; q++) {
            int i  = tid + q * THREADS;
            int r  = i / (BK / 4);
            int c4 = (i % (BK / 4)) * 4;
            As[buf][c4 + 0][r] = aReg[q].x;
            As[buf][c4 + 1][r] = aReg[q].y;
            As[buf][c4 + 2][r] = aReg[q].z;
            As[buf][c4 + 3][r] = aReg[q].w;
        }
#pragma unroll
        for (int q = 0; q < B_LD; q++) {
            int i = tid + q * THREADS;
            int r = i / (BN / 4);
            int c = (i % (BN / 4)) * 4;
            *reinterpret_cast<float4*>(&Bs[buf][r][c]) = bReg[q];
        }
    };

    float acc[TM][TN];
#pragma unroll
    for (int i = 0; i < TM; i++)
#pragma unroll
        for (int j = 0; j < TN; j++) acc[i][j] = 0.f;

    auto compute = [&](int buf) {
#pragma unroll
        for (int k = 0; k < BK; k++) {
            float aR[TM], bR[TN];
#pragma unroll
            for (int i = 0; i < TM; i += 4) {
                float4 v = *reinterpret_cast<const float4*>(&As[buf][k][ty * TM + i]);
                aR[i + 0] = v.x; aR[i + 1] = v.y; aR[i + 2] = v.z; aR[i + 3] = v.w;
            }
#pragma unroll
            for (int j = 0; j < TN; j += 4) {
                float4 v = *reinterpret_cast<const float4*>(&Bs[buf][k][tx * TN + j]);
                bR[j + 0] = v.x; bR[j + 1] = v.y; bR[j + 2] = v.z; bR[j + 3] = v.w;
            }
#pragma unroll
            for (int i = 0; i < TM; i++)
#pragma unroll
                for (int j = 0; j < TN; j++)
                    acc[i][j] = fmaf(aR[i], bR[j], acc[i][j]);
        }
    };

    fetch(0);
    stage(0);
    __syncthreads();
    int buf = 0;
    for (int k0 = BK; k0 < K; k0 += BK) {
        fetch(k0);            // global loads issue; latency hidden by compute
        compute(buf);
        stage(buf ^ 1);
        __syncthreads();
        buf ^= 1;
    }
    compute(buf);

#pragma unroll
    for (int i = 0; i < TM; i++) {
        int r = row0 + ty * TM + i;
        if (r < M) {
#pragma unroll
            for (int j = 0; j < TN; j += 4) {
                float4 v = make_float4(acc[i][j], acc[i][j + 1], acc[i][j + 2], acc[i][j + 3]);
                *reinterpret_cast<float4*>(C + (size_t)r * N + col0 + tx * TN + j) = v;
            }
        }
    }
}

__global__ void __launch_bounds__(256)
sgemm1_kernel(const float* __restrict__ A, const float* __restrict__ B,
              int M, int N, int K) {
    sgemm_body<128, 128, 16, 8, 8>(A, B, g_h1, M, N, K);
}

__global__ void __launch_bounds__(256)
sgemm2_kernel(const float* __restrict__ B, int M, int N, int K) {
    sgemm_body<128, 64, 16, 8, 4>(g_x2, B, g_h2, M, N, K);
}

// ---------------------------------------------------------------------------
// alpha_s[n,h] = <h[n,h,:], a_src[h,:]>,  alpha_d likewise.  One warp / node.
// ---------------------------------------------------------------------------
template <int H, int C>
__device__ __forceinline__ void alpha_body(const float* __restrict__ hfeat,
                                           const float* __restrict__ a_src,
                                           const float* __restrict__ a_dst,
                                           float* __restrict__ as_out,
                                           float* __restrict__ ad_out, int Nn) {
    constexpr int HC  = H * C;
    constexpr int CPL = HC / 32;   // channels per lane
    constexpr int LPH = 32 / H;    // lanes per head
    int warp = (blockIdx.x * blockDim.x + threadIdx.x) >> 5;
    int lane = threadIdx.x & 31;
    if (warp >= Nn) return;

    const float* hp = hfeat + (size_t)warp * HC + lane * CPL;
    float ss = 0.f, sd = 0.f;
#pragma unroll
    for (int k = 0; k < CPL; k++) {
        float v = hp[k];
        ss = fmaf(v, a_src[lane * CPL + k], ss);
        sd = fmaf(v, a_dst[lane * CPL + k], sd);
    }
#pragma unroll
    for (int o = LPH / 2; o > 0; o >>= 1) {
        ss += __shfl_xor_sync(0xFFFFFFFFu, ss, o);
        sd += __shfl_xor_sync(0xFFFFFFFFu, sd, o);
    }
    if ((lane % LPH) == 0) {
        int head = lane / LPH;
        as_out[warp * H + head] = ss;
        ad_out[warp * H + head] = sd;
    }
}

__global__ void alpha1_kernel(const float* __restrict__ a_src,
                              const float* __restrict__ a_dst, int Nn) {
    alpha_body<4, 64>(g_h1, a_src, a_dst, g_as1, g_ad1, Nn);
}

__global__ void alpha2_kernel(const float* __restrict__ a_src,
                              const float* __restrict__ a_dst, int Nn) {
    alpha_body<1, 64>(g_h2, a_src, a_dst, g_as2, g_ad2, Nn);
}

// ---------------------------------------------------------------------------
// SINGLE-PASS per-node softmax + weighted aggregation.  One warp / node.
// Key identity: out = (sum_e exp(e)*h[src_e]) / (sum_e exp(e) + 1e-16).
// Every lane iterates ALL edges of its node (it owns CPL channels), so it
// accumulates the full denominator locally -> no separate edge pass, no
// shuffle reduction. Max-free exp is safe: |e| is bounded (~<10).
// ---------------------------------------------------------------------------
template <int H, int C, bool RELU>
__device__ __forceinline__ void aggregate_body(const float* __restrict__ hfeat,
                                               const float* __restrict__ as_in,
                                               const float* __restrict__ ad_in,
                                               const float* __restrict__ bias,
                                               float* __restrict__ out, int Nn) {
    constexpr int HC  = H * C;
    constexpr int CPL = HC / 32;     // 8 (layer1) or 2 (layer2)
    int warp = (blockIdx.x * blockDim.x + threadIdx.x) >> 5;
    int lane = threadIdx.x & 31;
    if (warp >= Nn) return;
    const int n   = warp;
    const int beg = g_rowptr[n];
    const int end = g_rowptr[n + 1];

    const int chan0 = lane * CPL;
    const int headL = chan0 / C;                   // head owning this lane
    const float adh = ad_in[n * H + headL];

    auto edge_w = [&](int s) -> float {            // unnormalized weight
        float e = as_in[s * H + headL] + adh;
        e = (e > 0.f) ? e : 0.2f * e;              // leaky_relu(0.2)
        return expf(e);
    };

    float acc[CPL];
#pragma unroll
    for (int k = 0; k < CPL; k++) acc[k] = 0.f;
    float denom = 0.f;

    int j = beg;
    // 4 edges in flight per iteration for memory-level parallelism
    for (; j + 3 < end; j += 4) {
        int   s[4];
        float a[4];
#pragma unroll
        for (int q = 0; q < 4; q++) s[q] = g_esrc[j + q];
#pragma unroll
        for (int q = 0; q < 4; q++) { a[q] = edge_w(s[q]); denom += a[q]; }
        if constexpr (CPL == 8) {
            float4 va[4], vb[4];
#pragma unroll
            for (int q = 0; q < 4; q++) {
                const float* p = hfeat + (size_t)s[q] * HC + chan0;
                va[q] = *reinterpret_cast<const float4*>(p);
                vb[q] = *reinterpret_cast<const float4*>(p + 4);
            }
#pragma unroll
            for (int q = 0; q < 4; q++) {
                acc[0] = fmaf(va[q].x, a[q], acc[0]);
                acc[1] = fmaf(va[q].y, a[q], acc[1]);
                acc[2] = fmaf(va[q].z, a[q], acc[2]);
                acc[3] = fmaf(va[q].w, a[q], acc[3]);
                acc[4] = fmaf(vb[q].x, a[q], acc[4]);
                acc[5] = fmaf(vb[q].y, a[q], acc[5]);
                acc[6] = fmaf(vb[q].z, a[q], acc[6]);
                acc[7] = fmaf(vb[q].w, a[q], acc[7]);
            }
        } else {
            float2 v[4];
#pragma unroll
            for (int q = 0; q < 4; q++)
                v[q] = *reinterpret_cast<const float2*>(hfeat + (size_t)s[q] * HC + chan0);
#pragma unroll
            for (int q = 0; q < 4; q++) {
                acc[0] = fmaf(v[q].x, a[q], acc[0]);
                acc[1] = fmaf(v[q].y, a[q], acc[1]);
            }
        }
    }
    for (; j < end; j++) {
        int s0 = g_esrc[j];
        float a0 = edge_w(s0);
        denom += a0;
        const float* p0 = hfeat + (size_t)s0 * HC + chan0;
        if constexpr (CPL == 8) {
            float4 v0a = *reinterpret_cast<const float4*>(p0);
            float4 v0b = *reinterpret_cast<const float4*>(p0 + 4);
            acc[0] = fmaf(v0a.x, a0, acc[0]); acc[1] = fmaf(v0a.y, a0, acc[1]);
            acc[2] = fmaf(v0a.z, a0, acc[2]); acc[3] = fmaf(v0a.w, a0, acc[3]);
            acc[4] = fmaf(v0b.x, a0, acc[4]); acc[5] = fmaf(v0b.y, a0, acc[5]);
            acc[6] = fmaf(v0b.z, a0, acc[6]); acc[7] = fmaf(v0b.w, a0, acc[7]);
        } else {
            float2 v0 = *reinterpret_cast<const float2*>(p0);
            acc[0] = fmaf(v0.x, a0, acc[0]); acc[1] = fmaf(v0.y, a0, acc[1]);
        }
    }

    // ---- epilogue: normalize, bias (+ optional relu), coalesced write ----
    const float inv = 1.0f / (denom + 1e-16f);
    float* op = out + (size_t)n * HC + chan0;
#pragma unroll
    for (int k = 0; k < CPL; k++) {
        float v = fmaf(acc[k], inv, bias[chan0 + k]);
        if constexpr (RELU) v = fmaxf(v, 0.f);
        op[k] = v;
    }
}

__global__ void agg1_kernel(const float* __restrict__ bias, int Nn) {
    aggregate_body<4, 64, true>(g_h1, g_as1, g_ad1, bias, g_x2, Nn);
}

__global__ void agg2_kernel(const float* __restrict__ bias,
                            float* __restrict__ out, int Nn) {
    aggregate_body<1, 64, false>(g_h2, g_as2, g_ad2, bias, out, Nn);
}

// ---------------------------------------------------------------------------
// kernel_launch — pure kernel launches, no runtime API calls.
// inputs: x, edge_index, W1, a_src1, a_dst1, b1, W2, a_src2, a_dst2, b2
// ---------------------------------------------------------------------------
extern "C" void kernel_launch(void* const* d_in, const int* in_sizes, int n_in,
                              void* d_out, int out_size) {
    const float* x      = (const float*)d_in[0];
    const int*   ei     = (const int*)d_in[1];     // int32 (JAX x64 disabled)
    const float* W1     = (const float*)d_in[2];
    const float* a_src1 = (const float*)d_in[3];
    const float* a_dst1 = (const float*)d_in[4];
    const float* b1     = (const float*)d_in[5];
    const float* W2     = (const float*)d_in[6];
    const float* a_src2 = (const float*)d_in[7];
    const float* a_dst2 = (const float*)d_in[8];
    const float* b2     = (const float*)d_in[9];

    const int C   = in_sizes[9];            // 64
    const int H   = in_sizes[3] / C;        // 4
    const int HC1 = H * C;                  // 256
    const int Fin = in_sizes[2] / HC1;      // 128
    const int Nn  = in_sizes[0] / Fin;      // 50000
    const int E   = in_sizes[1] / 2;        // 800000
    const int Etot = E + Nn;

    if (Nn > NMAX || Etot > EMAX || H != 4 || C != 64) return;

    // ---- build dst-sorted CSR (counting sort) ----
    zero_deg_kernel<<<(Nn + 255) / 256, 256>>>(Nn);
    count_kernel<<<(Etot + 255) / 256, 256>>>(ei, E, Nn);
    scan_kernel<<<1, 1024>>>(Nn);
    fill_kernel<<<(Etot + 255) / 256, 256>>>(ei, E, Nn);

    const int warpBlocks = (Nn + 7) / 8;    // 8 warps / 256-thread block

    // ---- layer 1 ----
    {
        dim3 grid(HC1 / 128, (Nn + 127) / 128);
        sgemm1_kernel<<<grid, 256>>>(x, W1, Nn, HC1, Fin);
    }
    alpha1_kernel<<<warpBlocks, 256>>>(a_src1, a_dst1, Nn);
    agg1_kernel<<<warpBlocks, 256>>>(b1, Nn);

    // ---- layer 2 ----
    {
        dim3 grid(C / 64, (Nn + 127) / 128);
        sgemm2_kernel<<<grid, 256>>>(W2, Nn, C, HC1);
    }
    alpha2_kernel<<<warpBlocks, 256>>>(a_src2, a_dst2, Nn);
    agg2_kernel<<<warpBlocks, 256>>>(b2, (float*)d_out, Nn);
}

// round 12
// speedup vs baseline: 1.5396x; 1.1064x over previous
#include <cuda_runtime.h>
#include <math.h>
#include <stdint.h>

// ---------------------------------------------------------------------------
// Static device scratch (no allocations allowed anywhere).
// Sized for N <= 65536 nodes, E_total <= 2.2M edges (instance: 50000 / 850000).
// ---------------------------------------------------------------------------
#define NMAX 65536
#define EMAX 2200000

__device__ float g_h1[(size_t)NMAX * 256];   // layer-1 features  h1 = x @ W1
__device__ float g_x2[(size_t)NMAX * 256];   // relu(agg1 + b1) = layer-2 input
__device__ float g_h2[(size_t)NMAX * 64];    // layer-2 features  h2 = x2 @ W2
__device__ float g_as1[NMAX * 4];
__device__ float g_ad1[NMAX * 4];
__device__ float g_as2[NMAX];
__device__ float g_ad2[NMAX];
__device__ int   g_deg[NMAX];
__device__ int   g_pos[NMAX];
__device__ int   g_rowptr[NMAX + 1];
__device__ int   g_esrc[EMAX];               // src node of each dst-sorted edge

// ---------------------------------------------------------------------------
// CSR construction (counting sort by destination). edge_index is INT32.
// ---------------------------------------------------------------------------
__global__ void zero_deg_kernel(int Nn) {
    int i = blockIdx.x * blockDim.x + threadIdx.x;
    if (i < Nn) g_deg[i] = 0;
}

__global__ void count_kernel(const int* __restrict__ ei, int E, int Nn) {
    int i = blockIdx.x * blockDim.x + threadIdx.x;
    int tot = E + Nn;
    if (i >= tot) return;
    int d = (i < E) ? ei[E + i] : (i - E);
    if ((unsigned)d < (unsigned)Nn) atomicAdd(&g_deg[d], 1);
}

__global__ void scan_kernel(int N) {
    __shared__ int ssum[1024];
    int tid = threadIdx.x;
    int chunk = (N + 1023) >> 10;
    int start = tid * chunk;
    int end = min(start + chunk, N);
    int s = 0;
    for (int i = start; i < end; i++) s += g_deg[i];
    ssum[tid] = s;
    __syncthreads();
    for (int off = 1; off < 1024; off <<= 1) {
        int v = (tid >= off) ? ssum[tid - off] : 0;
        __syncthreads();
        ssum[tid] += v;
        __syncthreads();
    }
    int run = (tid > 0) ? ssum[tid - 1] : 0;
    for (int i = start; i < end; i++) {
        g_rowptr[i] = run;
        g_pos[i] = run;
        run += g_deg[i];
    }
    if (start < N && end == N) g_rowptr[N] = run;
}

__global__ void fill_kernel(const int* __restrict__ ei, int E, int Nn) {
    int i = blockIdx.x * blockDim.x + threadIdx.x;
    int tot = E + Nn;
    if (i >= tot) return;
    int s, d;
    if (i < E) { s = ei[i]; d = ei[E + i]; }
    else       { s = d = i - E; }
    if ((unsigned)d >= (unsigned)Nn || (unsigned)s >= (unsigned)Nn) return;
    int slot = atomicAdd(&g_pos[d], 1);
    g_esrc[slot] = s;
}

// ---------------------------------------------------------------------------
// Double-buffered fp32 SGEMM: C[M,N] = A[M,K] @ B[K,N]  (row-major)
// 256 threads, BK=16, register-staged global prefetch overlaps the next
// tile's loads with the current tile's 1024 FMAs/thread. One sync / k-tile.
// (Proven fastest variant: rounds 8/11.)
// ---------------------------------------------------------------------------
template <int BM, int BN, int BK, int TM, int TN>
__device__ __forceinline__ void sgemm_body(const float* __restrict__ A,
                                           const float* __restrict__ B,
                                           float* __restrict__ C,
                                           int M, int N, int K) {
    constexpr int THREADS = (BM / TM) * (BN / TN);   // 256
    constexpr int A_LD = BM * BK / (4 * THREADS);    // float4 loads per thread
    constexpr int B_LD = BK * BN / (4 * THREADS);
    constexpr int TXN = BN / TN;                     // threads along N

    __shared__ float As[2][BK][BM];
    __shared__ float Bs[2][BK][BN];

    const int tid  = threadIdx.x;
    const int row0 = blockIdx.y * BM;
    const int col0 = blockIdx.x * BN;
    const int tx = tid % TXN;
    const int ty = tid / TXN;

    float4 aReg[A_LD], bReg[B_LD];

    auto fetch = [&](int k0) {
#pragma unroll
        for (int q = 0; q < A_LD; q++) {
            int i  = tid + q * THREADS;
            int r  = i / (BK / 4);
            int c4 = (i % (BK / 4)) * 4;
            aReg[q] = make_float4(0.f, 0.f, 0.f, 0.f);
            if (row0 + r < M)
                aReg[q] = *reinterpret_cast<const float4*>(
                    A + (size_t)(row0 + r) * K + k0 + c4);
        }
#pragma unroll
        for (int q = 0; q < B_LD; q++) {
            int i = tid + q * THREADS;
            int r = i / (BN / 4);
            int c = (i % (BN / 4)) * 4;
            bReg[q] = *reinterpret_cast<const float4*>(
                B + (size_t)(k0 + r) * N + col0 + c);
        }
    };
    auto stage = [&](int buf) {
#pragma unroll
        for (int q = 0; q < A_LD; q++) {
            int i  = tid + q * THREADS;
            int r  = i / (BK / 4);
            int c4 = (i % (BK / 4)) * 4;
            As[buf][c4 + 0][r] = aReg[q].x;
            As[buf][c4 + 1][r] = aReg[q].y;
            As[buf][c4 + 2][r] = aReg[q].z;
            As[buf][c4 + 3][r] = aReg[q].w;
        }
#pragma unroll
        for (int q = 0; q < B_LD; q++) {
            int i = tid + q * THREADS;
            int r = i / (BN / 4);
            int c = (i % (BN / 4)) * 4;
            *reinterpret_cast<float4*>(&Bs[buf][r][c]) = bReg[q];
        }
    };

    float acc[TM][TN];
#pragma unroll
    for (int i = 0; i < TM; i++)
#pragma unroll
        for (int j = 0; j < TN; j++) acc[i][j] = 0.f;

    auto compute = [&](int buf) {
#pragma unroll
        for (int k = 0; k < BK; k++) {
            float aR[TM], bR[TN];
#pragma unroll
            for (int i = 0; i < TM; i += 4) {
                float4 v = *reinterpret_cast<const float4*>(&As[buf][k][ty * TM + i]);
                aR[i + 0] = v.x; aR[i + 1] = v.y; aR[i + 2] = v.z; aR[i + 3] = v.w;
            }
#pragma unroll
            for (int j = 0; j < TN; j += 4) {
                float4 v = *reinterpret_cast<const float4*>(&Bs[buf][k][tx * TN + j]);
                bR[j + 0] = v.x; bR[j + 1] = v.y; bR[j + 2] = v.z; bR[j + 3] = v.w;
            }
#pragma unroll
            for (int i = 0; i < TM; i++)
#pragma unroll
                for (int j = 0; j < TN; j++)
                    acc[i][j] = fmaf(aR[i], bR[j], acc[i][j]);
        }
    };

    fetch(0);
    stage(0);
    __syncthreads();
    int buf = 0;
    for (int k0 = BK; k0 < K; k0 += BK) {
        fetch(k0);            // global loads issue; latency hidden by compute
        compute(buf);
        stage(buf ^ 1);
        __syncthreads();
        buf ^= 1;
    }
    compute(buf);

#pragma unroll
    for (int i = 0; i < TM; i++) {
        int r = row0 + ty * TM + i;
        if (r < M) {
#pragma unroll
            for (int j = 0; j < TN; j += 4) {
                float4 v = make_float4(acc[i][j], acc[i][j + 1], acc[i][j + 2], acc[i][j + 3]);
                *reinterpret_cast<float4*>(C + (size_t)r * N + col0 + tx * TN + j) = v;
            }
        }
    }
}

__global__ void __launch_bounds__(256)
sgemm1_kernel(const float* __restrict__ A, const float* __restrict__ B,
              int M, int N, int K) {
    sgemm_body<128, 128, 16, 8, 8>(A, B, g_h1, M, N, K);
}

__global__ void __launch_bounds__(256)
sgemm2_kernel(const float* __restrict__ B, int M, int N, int K) {
    sgemm_body<128, 64, 16, 8, 4>(g_x2, B, g_h2, M, N, K);
}

// ---------------------------------------------------------------------------
// alpha_s[n,h] = <h[n,h,:], a_src[h,:]>,  alpha_d likewise.  One warp / node.
// ---------------------------------------------------------------------------
template <int H, int C>
__device__ __forceinline__ void alpha_body(const float* __restrict__ hfeat,
                                           const float* __restrict__ a_src,
                                           const float* __restrict__ a_dst,
                                           float* __restrict__ as_out,
                                           float* __restrict__ ad_out, int Nn) {
    constexpr int HC  = H * C;
    constexpr int CPL = HC / 32;   // channels per lane
    constexpr int LPH = 32 / H;    // lanes per head
    int warp = (blockIdx.x * blockDim.x + threadIdx.x) >> 5;
    int lane = threadIdx.x & 31;
    if (warp >= Nn) return;

    const float* hp = hfeat + (size_t)warp * HC + lane * CPL;
    float ss = 0.f, sd = 0.f;
#pragma unroll
    for (int k = 0; k < CPL; k++) {
        float v = hp[k];
        ss = fmaf(v, a_src[lane * CPL + k], ss);
        sd = fmaf(v, a_dst[lane * CPL + k], sd);
    }
#pragma unroll
    for (int o = LPH / 2; o > 0; o >>= 1) {
        ss += __shfl_xor_sync(0xFFFFFFFFu, ss, o);
        sd += __shfl_xor_sync(0xFFFFFFFFu, sd, o);
    }
    if ((lane % LPH) == 0) {
        int head = lane / LPH;
        as_out[warp * H + head] = ss;
        ad_out[warp * H + head] = sd;
    }
}

__global__ void alpha1_kernel(const float* __restrict__ a_src,
                              const float* __restrict__ a_dst, int Nn) {
    alpha_body<4, 64>(g_h1, a_src, a_dst, g_as1, g_ad1, Nn);
}

__global__ void alpha2_kernel(const float* __restrict__ a_src,
                              const float* __restrict__ a_dst, int Nn) {
    alpha_body<1, 64>(g_h2, a_src, a_dst, g_as2, g_ad2, Nn);
}

// ---------------------------------------------------------------------------
// SINGLE-PASS per-node softmax + weighted aggregation.  One warp / node.
// out = (sum_e exp(e)*h[src_e]) / (sum_e exp(e) + 1e-16); every lane sees all
// edges of its node, so the denominator accumulates locally (no extra pass).
// Max-free exp is safe: |e| is bounded (~<10).
// ---------------------------------------------------------------------------
template <int H, int C, bool RELU>
__device__ __forceinline__ void aggregate_body(const float* __restrict__ hfeat,
                                               const float* __restrict__ as_in,
                                               const float* __restrict__ ad_in,
                                               const float* __restrict__ bias,
                                               float* __restrict__ out, int Nn) {
    constexpr int HC  = H * C;
    constexpr int CPL = HC / 32;     // 8 (layer1) or 2 (layer2)
    int warp = (blockIdx.x * blockDim.x + threadIdx.x) >> 5;
    int lane = threadIdx.x & 31;
    if (warp >= Nn) return;
    const int n   = warp;
    const int beg = g_rowptr[n];
    const int end = g_rowptr[n + 1];

    const int chan0 = lane * CPL;
    const int headL = chan0 / C;                   // head owning this lane
    const float adh = ad_in[n * H + headL];

    auto edge_w = [&](int s) -> float {            // unnormalized weight
        float e = as_in[s * H + headL] + adh;
        e = (e > 0.f) ? e : 0.2f * e;              // leaky_relu(0.2)
        return expf(e);
    };

    float acc[CPL];
#pragma unroll
    for (int k = 0; k < CPL; k++) acc[k] = 0.f;
    float denom = 0.f;

    int j = beg;
    for (; j + 3 < end; j += 4) {
        int   s[4];
        float a[4];
#pragma unroll
        for (int q = 0; q < 4; q++) s[q] = g_esrc[j + q];
#pragma unroll
        for (int q = 0; q < 4; q++) { a[q] = edge_w(s[q]); denom += a[q]; }
        if constexpr (CPL == 8) {
            float4 va[4], vb[4];
#pragma unroll
            for (int q = 0; q < 4; q++) {
                const float* p = hfeat + (size_t)s[q] * HC + chan0;
                va[q] = *reinterpret_cast<const float4*>(p);
                vb[q] = *reinterpret_cast<const float4*>(p + 4);
            }
#pragma unroll
            for (int q = 0; q < 4; q++) {
                acc[0] = fmaf(va[q].x, a[q], acc[0]);
                acc[1] = fmaf(va[q].y, a[q], acc[1]);
                acc[2] = fmaf(va[q].z, a[q], acc[2]);
                acc[3] = fmaf(va[q].w, a[q], acc[3]);
                acc[4] = fmaf(vb[q].x, a[q], acc[4]);
                acc[5] = fmaf(vb[q].y, a[q], acc[5]);
                acc[6] = fmaf(vb[q].z, a[q], acc[6]);
                acc[7] = fmaf(vb[q].w, a[q], acc[7]);
            }
        } else {
            float2 v[4];
#pragma unroll
            for (int q = 0; q < 4; q++)
                v[q] = *reinterpret_cast<const float2*>(hfeat + (size_t)s[q] * HC + chan0);
#pragma unroll
            for (int q = 0; q < 4; q++) {
                acc[0] = fmaf(v[q].x, a[q], acc[0]);
                acc[1] = fmaf(v[q].y, a[q], acc[1]);
            }
        }
    }
    for (; j < end; j++) {
        int s0 = g_esrc[j];
        float a0 = edge_w(s0);
        denom += a0;
        const float* p0 = hfeat + (size_t)s0 * HC + chan0;
        if constexpr (CPL == 8) {
            float4 v0a = *reinterpret_cast<const float4*>(p0);
            float4 v0b = *reinterpret_cast<const float4*>(p0 + 4);
            acc[0] = fmaf(v0a.x, a0, acc[0]); acc[1] = fmaf(v0a.y, a0, acc[1]);
            acc[2] = fmaf(v0a.z, a0, acc[2]); acc[3] = fmaf(v0a.w, a0, acc[3]);
            acc[4] = fmaf(v0b.x, a0, acc[4]); acc[5] = fmaf(v0b.y, a0, acc[5]);
            acc[6] = fmaf(v0b.z, a0, acc[6]); acc[7] = fmaf(v0b.w, a0, acc[7]);
        } else {
            float2 v0 = *reinterpret_cast<const float2*>(p0);
            acc[0] = fmaf(v0.x, a0, acc[0]); acc[1] = fmaf(v0.y, a0, acc[1]);
        }
    }

    const float inv = 1.0f / (denom + 1e-16f);
    float* op = out + (size_t)n * HC + chan0;
#pragma unroll
    for (int k = 0; k < CPL; k++) {
        float v = fmaf(acc[k], inv, bias[chan0 + k]);
        if constexpr (RELU) v = fmaxf(v, 0.f);
        op[k] = v;
    }
}

__global__ void agg1_kernel(const float* __restrict__ bias, int Nn) {
    aggregate_body<4, 64, true>(g_h1, g_as1, g_ad1, bias, g_x2, Nn);
}

__global__ void agg2_kernel(const float* __restrict__ bias,
                            float* __restrict__ out, int Nn) {
    aggregate_body<1, 64, false>(g_h2, g_as2, g_ad2, bias, out, Nn);
}

// ---------------------------------------------------------------------------
// kernel_launch — forked-stream DAG:
//   main stream: sgemm1 -> alpha1 -> [join] agg1 -> sgemm2 -> alpha2 -> agg2
//   side stream: zero -> count -> scan -> fill  (CSR build, independent)
// Standard capture-fork pattern (event fork from the capturing stream, event
// join before first consumer). Kernels identical to the 413us round-11 code.
// ---------------------------------------------------------------------------
extern "C" void kernel_launch(void* const* d_in, const int* in_sizes, int n_in,
                              void* d_out, int out_size) {
    const float* x      = (const float*)d_in[0];
    const int*   ei     = (const int*)d_in[1];     // int32 (JAX x64 disabled)
    const float* W1     = (const float*)d_in[2];
    const float* a_src1 = (const float*)d_in[3];
    const float* a_dst1 = (const float*)d_in[4];
    const float* b1     = (const float*)d_in[5];
    const float* W2     = (const float*)d_in[6];
    const float* a_src2 = (const float*)d_in[7];
    const float* a_dst2 = (const float*)d_in[8];
    const float* b2     = (const float*)d_in[9];

    const int C   = in_sizes[9];            // 64
    const int H   = in_sizes[3] / C;        // 4
    const int HC1 = H * C;                  // 256
    const int Fin = in_sizes[2] / HC1;      // 128
    const int Nn  = in_sizes[0] / Fin;      // 50000
    const int E   = in_sizes[1] / 2;        // 800000
    const int Etot = E + Nn;

    if (Nn > NMAX || Etot > EMAX || H != 4 || C != 64) return;

    cudaStream_t s1;
    cudaStreamCreateWithFlags(&s1, cudaStreamNonBlocking);
    cudaEvent_t evFork, evCsr;
    cudaEventCreateWithFlags(&evFork, cudaEventDisableTiming);
    cudaEventCreateWithFlags(&evCsr, cudaEventDisableTiming);

    // fork: side stream branches off the (possibly capturing) main stream
    cudaEventRecord(evFork, 0);
    cudaStreamWaitEvent(s1, evFork, 0);

    // ---- CSR build on side stream ----
    zero_deg_kernel<<<(Nn + 255) / 256, 256, 0, s1>>>(Nn);
    count_kernel<<<(Etot + 255) / 256, 256, 0, s1>>>(ei, E, Nn);
    scan_kernel<<<1, 1024, 0, s1>>>(Nn);

    // ---- GEMM1 on main stream (concurrent with CSR) ----
    {
        dim3 grid(HC1 / 128, (Nn + 127) / 128);
        sgemm1_kernel<<<grid, 256>>>(x, W1, Nn, HC1, Fin);
    }

    fill_kernel<<<(Etot + 255) / 256, 256, 0, s1>>>(ei, E, Nn);
    cudaEventRecord(evCsr, s1);

    const int warpBlocks = (Nn + 7) / 8;    // 8 warps / 256-thread block
    alpha1_kernel<<<warpBlocks, 256>>>(a_src1, a_dst1, Nn);

    // join: agg1 needs CSR (rowptr/esrc) + alpha1
    cudaStreamWaitEvent(0, evCsr, 0);
    agg1_kernel<<<warpBlocks, 256>>>(b1, Nn);

    // ---- layer 2 (serial chain on main stream) ----
    {
        dim3 grid(C / 64, (Nn + 127) / 128);
        sgemm2_kernel<<<grid, 256>>>(W2, Nn, C, HC1);
    }
    alpha2_kernel<<<warpBlocks, 256>>>(a_src2, a_dst2, Nn);
    agg2_kernel<<<warpBlocks, 256>>>(b2, (float*)d_out, Nn);
}

// round 13
// speedup vs baseline: 1.9419x; 1.2613x over previous
#include <cuda_runtime.h>
#include <cuda_bf16.h>
#include <math.h>
#include <stdint.h>

// ---------------------------------------------------------------------------
// Static device scratch (no allocations allowed anywhere).
// Instance: N=50000, E=800000 (+N self loops), Fin=128, H=4, C=64.
// ---------------------------------------------------------------------------
#define NMAX 65536
#define EMAX 2200000

__device__ float g_h1[(size_t)NMAX * 256];         // layer-1 features (fp32)
__device__ float g_h2[(size_t)NMAX * 64];          // layer-2 features (fp32)
__device__ __nv_bfloat16 g_xh[(size_t)NMAX * 128]; // x split hi
__device__ __nv_bfloat16 g_xl[(size_t)NMAX * 128]; // x split lo
__device__ __nv_bfloat16 g_x2h[(size_t)NMAX * 256];// relu(agg1+b1) split hi
__device__ __nv_bfloat16 g_x2l[(size_t)NMAX * 256];// relu(agg1+b1) split lo
__device__ __nv_bfloat16 g_w1h[128 * 256], g_w1l[128 * 256];
__device__ __nv_bfloat16 g_w2h[256 * 64],  g_w2l[256 * 64];
__device__ float g_as1[NMAX * 4];
__device__ float g_ad1[NMAX * 4];
__device__ float g_as2[NMAX];
__device__ float g_ad2[NMAX];
__device__ int   g_deg[NMAX];
__device__ int   g_pos[NMAX];
__device__ int   g_rowptr[NMAX + 1];
__device__ int   g_esrc[EMAX];

// ---------------------------------------------------------------------------
// CSR construction (counting sort by destination). edge_index is INT32.
// ---------------------------------------------------------------------------
__global__ void zero_deg_kernel(int Nn) {
    int i = blockIdx.x * blockDim.x + threadIdx.x;
    if (i < Nn) g_deg[i] = 0;
}

__global__ void count_kernel(const int* __restrict__ ei, int E, int Nn) {
    int i = blockIdx.x * blockDim.x + threadIdx.x;
    int tot = E + Nn;
    if (i >= tot) return;
    int d = (i < E) ? ei[E + i] : (i - E);
    if ((unsigned)d < (unsigned)Nn) atomicAdd(&g_deg[d], 1);
}

__global__ void scan_kernel(int N) {
    __shared__ int ssum[1024];
    int tid = threadIdx.x;
    int chunk = (N + 1023) >> 10;
    int start = tid * chunk;
    int end = min(start + chunk, N);
    int s = 0;
    for (int i = start; i < end; i++) s += g_deg[i];
    ssum[tid] = s;
    __syncthreads();
    for (int off = 1; off < 1024; off <<= 1) {
        int v = (tid >= off) ? ssum[tid - off] : 0;
        __syncthreads();
        ssum[tid] += v;
        __syncthreads();
    }
    int run = (tid > 0) ? ssum[tid - 1] : 0;
    for (int i = start; i < end; i++) {
        g_rowptr[i] = run;
        g_pos[i] = run;
        run += g_deg[i];
    }
    if (start < N && end == N) g_rowptr[N] = run;
}

__global__ void fill_kernel(const int* __restrict__ ei, int E, int Nn) {
    int i = blockIdx.x * blockDim.x + threadIdx.x;
    int tot = E + Nn;
    if (i >= tot) return;
    int s, d;
    if (i < E) { s = ei[i]; d = ei[E + i]; }
    else       { s = d = i - E; }
    if ((unsigned)d >= (unsigned)Nn || (unsigned)s >= (unsigned)Nn) return;
    int slot = atomicAdd(&g_pos[d], 1);
    g_esrc[slot] = s;
}

// ---------------------------------------------------------------------------
// fp32 -> (bf16 hi, bf16 lo) split:  v = hi + lo + O(2^-17 v)
// Covers x, W1, W2 in one grid-stride kernel.
// ---------------------------------------------------------------------------
__device__ __forceinline__ void split1(float v, __nv_bfloat16* ph, __nv_bfloat16* pl) {
    __nv_bfloat16 h = __float2bfloat16(v);
    *ph = h;
    *pl = __float2bfloat16(v - __bfloat162float(h));
}

__global__ void split3_kernel(const float* __restrict__ x,
                              const float* __restrict__ W1,
                              const float* __restrict__ W2, int nx) {
    const int NW1 = 128 * 256, NW2 = 256 * 64;
    int total = nx + NW1 + NW2;
    for (int i = blockIdx.x * blockDim.x + threadIdx.x; i < total;
         i += gridDim.x * blockDim.x) {
        if (i < nx)            split1(x[i],        &g_xh[i],        &g_xl[i]);
        else if (i < nx + NW1) split1(W1[i - nx],  &g_w1h[i - nx],  &g_w1l[i - nx]);
        else                   split1(W2[i-nx-NW1],&g_w2h[i-nx-NW1],&g_w2l[i-nx-NW1]);
    }
}

// ---------------------------------------------------------------------------
// bf16 tensor-core GEMM (3-term split): C = (Ah+Al) @ (Bh+Bl), fp32 accum.
//   C[M,N] = A[M,K] @ B[K,N], all row-major; A/B given as bf16 hi/lo pairs.
// BM=128, BK=16, 256 threads = 8 warps (4 x WGN). Smem holds each k-tile as
// contiguous 128B 8x8 bf16 matrices -> ldmatrix.x4 fragments, conflict-free.
// Staging via cp.async (16B chunks). mma.m16n8k16: 3 mma per (hi,lo) pair.
// ---------------------------------------------------------------------------
__device__ __forceinline__ void ldsm_x4(uint32_t r[4], uint32_t addr) {
    asm volatile("ldmatrix.sync.aligned.m8n8.x4.shared.b16 {%0,%1,%2,%3}, [%4];"
                 : "=r"(r[0]), "=r"(r[1]), "=r"(r[2]), "=r"(r[3]) : "r"(addr));
}
__device__ __forceinline__ void ldsm_x4_t(uint32_t r[4], uint32_t addr) {
    asm volatile("ldmatrix.sync.aligned.m8n8.x4.trans.shared.b16 {%0,%1,%2,%3}, [%4];"
                 : "=r"(r[0]), "=r"(r[1]), "=r"(r[2]), "=r"(r[3]) : "r"(addr));
}
__device__ __forceinline__ void mma_bf16(float c[4], const uint32_t a[4],
                                         uint32_t b0, uint32_t b1) {
    asm volatile(
        "mma.sync.aligned.m16n8k16.row.col.f32.bf16.bf16.f32 "
        "{%0,%1,%2,%3}, {%4,%5,%6,%7}, {%8,%9}, {%0,%1,%2,%3};\n"
        : "+f"(c[0]), "+f"(c[1]), "+f"(c[2]), "+f"(c[3])
        : "r"(a[0]), "r"(a[1]), "r"(a[2]), "r"(a[3]), "r"(b0), "r"(b1));
}
__device__ __forceinline__ void cp16(uint32_t dst, const void* src, int sz) {
    asm volatile("cp.async.cg.shared.global [%0], [%1], 16, %2;"
                 :: "r"(dst), "l"(src), "r"(sz));
}
#define CP_COMMIT() asm volatile("cp.async.commit_group;" ::: "memory")
#define CP_WAIT0()  asm volatile("cp.async.wait_group 0;" ::: "memory")

template <int BN, int WN>
__device__ __forceinline__ void mma_gemm_body(const __nv_bfloat16* __restrict__ Ah,
                                              const __nv_bfloat16* __restrict__ Al,
                                              const __nv_bfloat16* __restrict__ Bh,
                                              const __nv_bfloat16* __restrict__ Bl,
                                              float* __restrict__ C,
                                              int M, int N, int K) {
    constexpr int BM  = 128;
    constexpr int NIC = BN / 8;           // 8x8 B matrices along N
    constexpr int NP  = WN / 16;          // ldmatrix.x4.trans per warp per k16
    constexpr int NBLK = WN / 8;          // n8-blocks per warp

    // smem: per buffer, A: 16mi x 2ki matrices (4KB), B: NIC x 2ki (BN*32 B)
    __shared__ uint4 sAh[2][256], sAl[2][256];
    __shared__ uint4 sBh[2][BN * 2], sBl[2][BN * 2];

    const int tid    = threadIdx.x;
    const int warpId = tid >> 5;
    const int lane   = tid & 31;
    const int row0 = blockIdx.y * BM;
    const int col0 = blockIdx.x * BN;

    // ---- producer mapping (per tile) ----
    const int aki = tid >> 7, ami = (tid >> 3) & 15, arow = tid & 7;
    const int aRowG = row0 + ami * 8 + arow;
    const int aDst  = (ami * 2 + aki) * 8 + arow;
    const int aszv  = (aRowG < M) ? 16 : 0;

    const bool bAct = (tid < BN * 2);
    const int bki  = tid / (NIC * 8);
    const int brem = tid % (NIC * 8);
    const int bni  = brem >> 3, brow = brem & 7;
    const int bDst = (bni * 2 + bki) * 8 + brow;
    const int bColG = col0 + bni * 8;

    uint32_t baseAh[2] = {(uint32_t)__cvta_generic_to_shared(&sAh[0][0]),
                          (uint32_t)__cvta_generic_to_shared(&sAh[1][0])};
    uint32_t baseAl[2] = {(uint32_t)__cvta_generic_to_shared(&sAl[0][0]),
                          (uint32_t)__cvta_generic_to_shared(&sAl[1][0])};
    uint32_t baseBh[2] = {(uint32_t)__cvta_generic_to_shared(&sBh[0][0]),
                          (uint32_t)__cvta_generic_to_shared(&sBh[1][0])};
    uint32_t baseBl[2] = {(uint32_t)__cvta_generic_to_shared(&sBl[0][0]),
                          (uint32_t)__cvta_generic_to_shared(&sBl[1][0])};

    auto loadTile = [&](int k0, int buf) {
        cp16(baseAh[buf] + aDst * 16, Ah + (size_t)aRowG * K + k0 + aki * 8, aszv);
        cp16(baseAl[buf] + aDst * 16, Al + (size_t)aRowG * K + k0 + aki * 8, aszv);
        if (bAct) {
            int kk = k0 + bki * 8 + brow;
            cp16(baseBh[buf] + bDst * 16, Bh + (size_t)kk * N + bColG, 16);
            cp16(baseBl[buf] + bDst * 16, Bl + (size_t)kk * N + bColG, 16);
        }
        CP_COMMIT();
    };

    // ---- consumer mapping ----
    const int mi0 = (warpId & 3) * 4;         // WM=32 -> 4 mi blocks
    const int ni0 = (warpId >> 2) * (WN / 8);
    const int q = lane >> 3, r8 = lane & 7;
    uint32_t aoff[2], boff[NP];
#pragma unroll
    for (int mt = 0; mt < 2; mt++)
        aoff[mt] = ((mi0 + mt * 2 + (q & 1)) * 2 + (q >> 1)) * 128 + r8 * 16;
#pragma unroll
    for (int np = 0; np < NP; np++)
        boff[np] = ((ni0 + np * 2 + (q >> 1)) * 2 + (q & 1)) * 128 + r8 * 16;

    float acc[2][NBLK][4];
#pragma unroll
    for (int mt = 0; mt < 2; mt++)
#pragma unroll
        for (int nb = 0; nb < NBLK; nb++)
#pragma unroll
            for (int e = 0; e < 4; e++) acc[mt][nb][e] = 0.f;

    const int KT = K >> 4;
    loadTile(0, 0);
    int buf = 0;
    for (int t = 0; t < KT; t++) {
        CP_WAIT0();
        __syncthreads();
        if (t + 1 < KT) loadTile((t + 1) << 4, buf ^ 1);

        uint32_t ah[2][4], al[2][4];
#pragma unroll
        for (int mt = 0; mt < 2; mt++) {
            ldsm_x4(ah[mt], baseAh[buf] + aoff[mt]);
            ldsm_x4(al[mt], baseAl[buf] + aoff[mt]);
        }
#pragma unroll
        for (int np = 0; np < NP; np++) {
            uint32_t bh[4], bl[4];
            ldsm_x4_t(bh, baseBh[buf] + boff[np]);
            ldsm_x4_t(bl, baseBl[buf] + boff[np]);
#pragma unroll
            for (int mt = 0; mt < 2; mt++)
#pragma unroll
                for (int s = 0; s < 2; s++) {
                    int nb = np * 2 + s;
                    mma_bf16(acc[mt][nb], ah[mt], bh[s * 2], bh[s * 2 + 1]); // hh
                    mma_bf16(acc[mt][nb], ah[mt], bl[s * 2], bl[s * 2 + 1]); // hl
                    mma_bf16(acc[mt][nb], al[mt], bh[s * 2], bh[s * 2 + 1]); // lh
                }
        }
        __syncthreads();
        buf ^= 1;
    }

    // ---- epilogue: c0/c1 at (r, c..c+1), c2/c3 at (r+8, c..c+1) ----
    const int g = lane >> 2, t4 = lane & 3;
#pragma unroll
    for (int mt = 0; mt < 2; mt++)
#pragma unroll
        for (int nb = 0; nb < NBLK; nb++) {
            int r = row0 + (warpId & 3) * 32 + mt * 16 + g;
            int c = col0 + (warpId >> 2) * WN + nb * 8 + 2 * t4;
            if (r < M)
                *reinterpret_cast<float2*>(C + (size_t)r * N + c) =
                    make_float2(acc[mt][nb][0], acc[mt][nb][1]);
            if (r + 8 < M)
                *reinterpret_cast<float2*>(C + (size_t)(r + 8) * N + c) =
                    make_float2(acc[mt][nb][2], acc[mt][nb][3]);
        }
}

__global__ void __launch_bounds__(256, 2)
sgemm1_kernel(int M, int N, int K) {
    mma_gemm_body<128, 64>(g_xh, g_xl, g_w1h, g_w1l, g_h1, M, N, K);
}

__global__ void __launch_bounds__(256, 2)
sgemm2_kernel(int M, int N, int K) {
    mma_gemm_body<64, 32>(g_x2h, g_x2l, g_w2h, g_w2l, g_h2, M, N, K);
}

// ---------------------------------------------------------------------------
// alpha_s[n,h] = <h[n,h,:], a_src[h,:]>,  alpha_d likewise.  One warp / node.
// ---------------------------------------------------------------------------
template <int H, int C>
__device__ __forceinline__ void alpha_body(const float* __restrict__ hfeat,
                                           const float* __restrict__ a_src,
                                           const float* __restrict__ a_dst,
                                           float* __restrict__ as_out,
                                           float* __restrict__ ad_out, int Nn) {
    constexpr int HC  = H * C;
    constexpr int CPL = HC / 32;
    constexpr int LPH = 32 / H;
    int warp = (blockIdx.x * blockDim.x + threadIdx.x) >> 5;
    int lane = threadIdx.x & 31;
    if (warp >= Nn) return;

    const float* hp = hfeat + (size_t)warp * HC + lane * CPL;
    float ss = 0.f, sd = 0.f;
#pragma unroll
    for (int k = 0; k < CPL; k++) {
        float v = hp[k];
        ss = fmaf(v, a_src[lane * CPL + k], ss);
        sd = fmaf(v, a_dst[lane * CPL + k], sd);
    }
#pragma unroll
    for (int o = LPH / 2; o > 0; o >>= 1) {
        ss += __shfl_xor_sync(0xFFFFFFFFu, ss, o);
        sd += __shfl_xor_sync(0xFFFFFFFFu, sd, o);
    }
    if ((lane % LPH) == 0) {
        int head = lane / LPH;
        as_out[warp * H + head] = ss;
        ad_out[warp * H + head] = sd;
    }
}

__global__ void alpha1_kernel(const float* __restrict__ a_src,
                              const float* __restrict__ a_dst, int Nn) {
    alpha_body<4, 64>(g_h1, a_src, a_dst, g_as1, g_ad1, Nn);
}

__global__ void alpha2_kernel(const float* __restrict__ a_src,
                              const float* __restrict__ a_dst, int Nn) {
    alpha_body<1, 64>(g_h2, a_src, a_dst, g_as2, g_ad2, Nn);
}

// ---------------------------------------------------------------------------
// SINGLE-PASS per-node softmax + weighted aggregation.  One warp / node.
// out = (sum_e exp(e)*h[src_e]) / (sum_e exp(e) + 1e-16).
// Layer 1 (BF16OUT): writes relu(out+b) as bf16 hi/lo pairs for the bf16 GEMM2.
// ---------------------------------------------------------------------------
template <int H, int C, bool RELU, bool BF16OUT>
__device__ __forceinline__ void aggregate_body(const float* __restrict__ hfeat,
                                               const float* __restrict__ as_in,
                                               const float* __restrict__ ad_in,
                                               const float* __restrict__ bias,
                                               float* __restrict__ out,
                                               __nv_bfloat16* __restrict__ outh,
                                               __nv_bfloat16* __restrict__ outl,
                                               int Nn) {
    constexpr int HC  = H * C;
    constexpr int CPL = HC / 32;     // 8 (layer1) or 2 (layer2)
    int warp = (blockIdx.x * blockDim.x + threadIdx.x) >> 5;
    int lane = threadIdx.x & 31;
    if (warp >= Nn) return;
    const int n   = warp;
    const int beg = g_rowptr[n];
    const int end = g_rowptr[n + 1];

    const int chan0 = lane * CPL;
    const int headL = chan0 / C;
    const float adh = ad_in[n * H + headL];

    auto edge_w = [&](int s) -> float {
        float e = as_in[s * H + headL] + adh;
        e = (e > 0.f) ? e : 0.2f * e;
        return expf(e);
    };

    float acc[CPL];
#pragma unroll
    for (int k = 0; k < CPL; k++) acc[k] = 0.f;
    float denom = 0.f;

    int j = beg;
    for (; j + 3 < end; j += 4) {
        int   s[4];
        float a[4];
#pragma unroll
        for (int q = 0; q < 4; q++) s[q] = g_esrc[j + q];
#pragma unroll
        for (int q = 0; q < 4; q++) { a[q] = edge_w(s[q]); denom += a[q]; }
        if constexpr (CPL == 8) {
            float4 va[4], vb[4];
#pragma unroll
            for (int q = 0; q < 4; q++) {
                const float* p = hfeat + (size_t)s[q] * HC + chan0;
                va[q] = *reinterpret_cast<const float4*>(p);
                vb[q] = *reinterpret_cast<const float4*>(p + 4);
            }
#pragma unroll
            for (int q = 0; q < 4; q++) {
                acc[0] = fmaf(va[q].x, a[q], acc[0]);
                acc[1] = fmaf(va[q].y, a[q], acc[1]);
                acc[2] = fmaf(va[q].z, a[q], acc[2]);
                acc[3] = fmaf(va[q].w, a[q], acc[3]);
                acc[4] = fmaf(vb[q].x, a[q], acc[4]);
                acc[5] = fmaf(vb[q].y, a[q], acc[5]);
                acc[6] = fmaf(vb[q].z, a[q], acc[6]);
                acc[7] = fmaf(vb[q].w, a[q], acc[7]);
            }
        } else {
            float2 v[4];
#pragma unroll
            for (int q = 0; q < 4; q++)
                v[q] = *reinterpret_cast<const float2*>(hfeat + (size_t)s[q] * HC + chan0);
#pragma unroll
            for (int q = 0; q < 4; q++) {
                acc[0] = fmaf(v[q].x, a[q], acc[0]);
                acc[1] = fmaf(v[q].y, a[q], acc[1]);
            }
        }
    }
    for (; j < end; j++) {
        int s0 = g_esrc[j];
        float a0 = edge_w(s0);
        denom += a0;
        const float* p0 = hfeat + (size_t)s0 * HC + chan0;
        if constexpr (CPL == 8) {
            float4 v0a = *reinterpret_cast<const float4*>(p0);
            float4 v0b = *reinterpret_cast<const float4*>(p0 + 4);
            acc[0] = fmaf(v0a.x, a0, acc[0]); acc[1] = fmaf(v0a.y, a0, acc[1]);
            acc[2] = fmaf(v0a.z, a0, acc[2]); acc[3] = fmaf(v0a.w, a0, acc[3]);
            acc[4] = fmaf(v0b.x, a0, acc[4]); acc[5] = fmaf(v0b.y, a0, acc[5]);
            acc[6] = fmaf(v0b.z, a0, acc[6]); acc[7] = fmaf(v0b.w, a0, acc[7]);
        } else {
            float2 v0 = *reinterpret_cast<const float2*>(p0);
            acc[0] = fmaf(v0.x, a0, acc[0]); acc[1] = fmaf(v0.y, a0, acc[1]);
        }
    }

    const float inv = 1.0f / (denom + 1e-16f);
    float v[CPL];
#pragma unroll
    for (int k = 0; k < CPL; k++) {
        float w = fmaf(acc[k], inv, bias[chan0 + k]);
        if constexpr (RELU) w = fmaxf(w, 0.f);
        v[k] = w;
    }

    if constexpr (BF16OUT) {
        // write 8 bf16 hi (16B) + 8 bf16 lo (16B), packed
        __nv_bfloat16 hb[CPL];
        float lof[CPL];
#pragma unroll
        for (int k = 0; k < CPL; k++) {
            hb[k] = __float2bfloat16(v[k]);
            lof[k] = v[k] - __bfloat162float(hb[k]);
        }
        uint4 uh, ul;
        {
            __nv_bfloat162 p0 = __halves2bfloat162(hb[0], hb[1]);
            __nv_bfloat162 p1 = __halves2bfloat162(hb[2], hb[3]);
            __nv_bfloat162 p2 = __halves2bfloat162(hb[4], hb[5]);
            __nv_bfloat162 p3 = __halves2bfloat162(hb[6], hb[7]);
            uh.x = *reinterpret_cast<uint32_t*>(&p0);
            uh.y = *reinterpret_cast<uint32_t*>(&p1);
            uh.z = *reinterpret_cast<uint32_t*>(&p2);
            uh.w = *reinterpret_cast<uint32_t*>(&p3);
        }
        {
            __nv_bfloat162 p0 = __floats2bfloat162_rn(lof[0], lof[1]);
            __nv_bfloat162 p1 = __floats2bfloat162_rn(lof[2], lof[3]);
            __nv_bfloat162 p2 = __floats2bfloat162_rn(lof[4], lof[5]);
            __nv_bfloat162 p3 = __floats2bfloat162_rn(lof[6], lof[7]);
            ul.x = *reinterpret_cast<uint32_t*>(&p0);
            ul.y = *reinterpret_cast<uint32_t*>(&p1);
            ul.z = *reinterpret_cast<uint32_t*>(&p2);
            ul.w = *reinterpret_cast<uint32_t*>(&p3);
        }
        *reinterpret_cast<uint4*>(outh + (size_t)n * HC + chan0) = uh;
        *reinterpret_cast<uint4*>(outl + (size_t)n * HC + chan0) = ul;
    } else {
        float* op = out + (size_t)n * HC + chan0;
#pragma unroll
        for (int k = 0; k < CPL; k++) op[k] = v[k];
    }
}

__global__ void agg1_kernel(const float* __restrict__ bias, int Nn) {
    aggregate_body<4, 64, true, true>(g_h1, g_as1, g_ad1, bias,
                                      nullptr, g_x2h, g_x2l, Nn);
}

__global__ void agg2_kernel(const float* __restrict__ bias,
                            float* __restrict__ out, int Nn) {
    aggregate_body<1, 64, false, false>(g_h2, g_as2, g_ad2, bias,
                                        out, nullptr, nullptr, Nn);
}

// ---------------------------------------------------------------------------
// kernel_launch — forked-stream DAG (R12 topology, proven -40us):
//   main: split3 -> sgemm1 -> alpha1 -> [join CSR] agg1 -> sgemm2 -> alpha2 -> agg2
//   side: zero -> count -> scan -> fill
// ---------------------------------------------------------------------------
extern "C" void kernel_launch(void* const* d_in, const int* in_sizes, int n_in,
                              void* d_out, int out_size) {
    const float* x      = (const float*)d_in[0];
    const int*   ei     = (const int*)d_in[1];     // int32 (JAX x64 disabled)
    const float* W1     = (const float*)d_in[2];
    const float* a_src1 = (const float*)d_in[3];
    const float* a_dst1 = (const float*)d_in[4];
    const float* b1     = (const float*)d_in[5];
    const float* W2     = (const float*)d_in[6];
    const float* a_src2 = (const float*)d_in[7];
    const float* a_dst2 = (const float*)d_in[8];
    const float* b2     = (const float*)d_in[9];

    const int C   = in_sizes[9];            // 64
    const int H   = in_sizes[3] / C;        // 4
    const int HC1 = H * C;                  // 256
    const int Fin = in_sizes[2] / HC1;      // 128
    const int Nn  = in_sizes[0] / Fin;      // 50000
    const int E   = in_sizes[1] / 2;        // 800000
    const int Etot = E + Nn;

    if (Nn > NMAX || Etot > EMAX || H != 4 || C != 64 || Fin != 128) return;

    cudaStream_t s1;
    cudaStreamCreateWithFlags(&s1, cudaStreamNonBlocking);
    cudaEvent_t evFork, evCsr;
    cudaEventCreateWithFlags(&evFork, cudaEventDisableTiming);
    cudaEventCreateWithFlags(&evCsr, cudaEventDisableTiming);

    cudaEventRecord(evFork, 0);
    cudaStreamWaitEvent(s1, evFork, 0);

    // ---- CSR build on side stream ----
    zero_deg_kernel<<<(Nn + 255) / 256, 256, 0, s1>>>(Nn);
    count_kernel<<<(Etot + 255) / 256, 256, 0, s1>>>(ei, E, Nn);
    scan_kernel<<<1, 1024, 0, s1>>>(Nn);

    // ---- main stream: split + GEMM1 ----
    {
        int nx = Nn * Fin;
        int total = nx + 128 * 256 + 256 * 64;
        split3_kernel<<<(total + 255) / 256, 256>>>(x, W1, W2, nx);
    }
    {
        dim3 grid(HC1 / 128, (Nn + 127) / 128);
        sgemm1_kernel<<<grid, 256>>>(Nn, HC1, Fin);
    }

    fill_kernel<<<(Etot + 255) / 256, 256, 0, s1>>>(ei, E, Nn);
    cudaEventRecord(evCsr, s1);

    const int warpBlocks = (Nn + 7) / 8;
    alpha1_kernel<<<warpBlocks, 256>>>(a_src1, a_dst1, Nn);

    cudaStreamWaitEvent(0, evCsr, 0);
    agg1_kernel<<<warpBlocks, 256>>>(b1, Nn);

    // ---- layer 2 ----
    {
        dim3 grid(C / 64, (Nn + 127) / 128);
        sgemm2_kernel<<<grid, 256>>>(Nn, C, HC1);
    }
    alpha2_kernel<<<warpBlocks, 256>>>(a_src2, a_dst2, Nn);
    agg2_kernel<<<warpBlocks, 256>>>(b2, (float*)d_out, Nn);
}

// round 14
// speedup vs baseline: 2.2482x; 1.1577x over previous
#include <cuda_runtime.h>
#include <cuda_bf16.h>
#include <cuda_fp16.h>
#include <math.h>
#include <stdint.h>

// ---------------------------------------------------------------------------
// Static device scratch (no allocations allowed anywhere).
// Instance: N=50000, E=800000 (+N self loops), Fin=128, H=4, C=64.
// ---------------------------------------------------------------------------
#define NMAX 65536
#define EMAX 2200000

__device__ __half g_h1[(size_t)NMAX * 256];        // layer-1 features (fp16)
__device__ __half g_h2[(size_t)NMAX * 64];         // layer-2 features (fp16)
__device__ __nv_bfloat16 g_xh[(size_t)NMAX * 128]; // x split hi
__device__ __nv_bfloat16 g_xl[(size_t)NMAX * 128]; // x split lo
__device__ __nv_bfloat16 g_x2h[(size_t)NMAX * 256];// relu(agg1+b1) split hi
__device__ __nv_bfloat16 g_x2l[(size_t)NMAX * 256];// relu(agg1+b1) split lo
__device__ __nv_bfloat16 g_w1h[128 * 256], g_w1l[128 * 256];
__device__ __nv_bfloat16 g_w2h[256 * 64],  g_w2l[256 * 64];
__device__ float g_as1[NMAX * 4];
__device__ float g_ad1[NMAX * 4];
__device__ float g_as2[NMAX];
__device__ float g_ad2[NMAX];
__device__ int   g_deg[NMAX];
__device__ int   g_pos[NMAX];
__device__ int   g_rowptr[NMAX + 1];
__device__ int   g_esrc[EMAX];

// ---------------------------------------------------------------------------
// CSR construction (counting sort by destination). edge_index is INT32.
// ---------------------------------------------------------------------------
__global__ void zero_deg_kernel(int Nn) {
    int i = blockIdx.x * blockDim.x + threadIdx.x;
    if (i < Nn) g_deg[i] = 0;
}

__global__ void count_kernel(const int* __restrict__ ei, int E, int Nn) {
    int i = blockIdx.x * blockDim.x + threadIdx.x;
    int tot = E + Nn;
    if (i >= tot) return;
    int d = (i < E) ? ei[E + i] : (i - E);
    if ((unsigned)d < (unsigned)Nn) atomicAdd(&g_deg[d], 1);
}

__global__ void scan_kernel(int N) {
    __shared__ int ssum[1024];
    int tid = threadIdx.x;
    int chunk = (N + 1023) >> 10;
    int start = tid * chunk;
    int end = min(start + chunk, N);
    int s = 0;
    for (int i = start; i < end; i++) s += g_deg[i];
    ssum[tid] = s;
    __syncthreads();
    for (int off = 1; off < 1024; off <<= 1) {
        int v = (tid >= off) ? ssum[tid - off] : 0;
        __syncthreads();
        ssum[tid] += v;
        __syncthreads();
    }
    int run = (tid > 0) ? ssum[tid - 1] : 0;
    for (int i = start; i < end; i++) {
        g_rowptr[i] = run;
        g_pos[i] = run;
        run += g_deg[i];
    }
    if (start < N && end == N) g_rowptr[N] = run;
}

__global__ void fill_kernel(const int* __restrict__ ei, int E, int Nn) {
    int i = blockIdx.x * blockDim.x + threadIdx.x;
    int tot = E + Nn;
    if (i >= tot) return;
    int s, d;
    if (i < E) { s = ei[i]; d = ei[E + i]; }
    else       { s = d = i - E; }
    if ((unsigned)d >= (unsigned)Nn || (unsigned)s >= (unsigned)Nn) return;
    int slot = atomicAdd(&g_pos[d], 1);
    g_esrc[slot] = s;
}

// ---------------------------------------------------------------------------
// fp32 -> (bf16 hi, bf16 lo) split, vectorized: 4 floats / thread.
// nx and the weight sizes are all multiples of 4, so groups never straddle.
// ---------------------------------------------------------------------------
__global__ void split3_kernel(const float* __restrict__ x,
                              const float* __restrict__ W1,
                              const float* __restrict__ W2, int nx) {
    const int NW1 = 128 * 256, NW2 = 256 * 64;
    int total4 = (nx + NW1 + NW2) >> 2;
    for (int i = blockIdx.x * blockDim.x + threadIdx.x; i < total4;
         i += gridDim.x * blockDim.x) {
        int base = i << 2;
        const float* src;
        __nv_bfloat16 *dh, *dl;
        if (base < nx)            { src = x + base;             dh = g_xh + base;        dl = g_xl + base; }
        else if (base < nx + NW1) { int o = base - nx;          src = W1 + o; dh = g_w1h + o; dl = g_w1l + o; }
        else                      { int o = base - nx - NW1;    src = W2 + o; dh = g_w2h + o; dl = g_w2l + o; }
        float4 v = *reinterpret_cast<const float4*>(src);
        __nv_bfloat16 h0 = __float2bfloat16(v.x), h1 = __float2bfloat16(v.y);
        __nv_bfloat16 h2 = __float2bfloat16(v.z), h3 = __float2bfloat16(v.w);
        __nv_bfloat162 hh0 = __halves2bfloat162(h0, h1);
        __nv_bfloat162 hh1 = __halves2bfloat162(h2, h3);
        __nv_bfloat162 ll0 = __floats2bfloat162_rn(v.x - __bfloat162float(h0),
                                                   v.y - __bfloat162float(h1));
        __nv_bfloat162 ll1 = __floats2bfloat162_rn(v.z - __bfloat162float(h2),
                                                   v.w - __bfloat162float(h3));
        uint2 uh, ul;
        uh.x = *reinterpret_cast<uint32_t*>(&hh0);
        uh.y = *reinterpret_cast<uint32_t*>(&hh1);
        ul.x = *reinterpret_cast<uint32_t*>(&ll0);
        ul.y = *reinterpret_cast<uint32_t*>(&ll1);
        *reinterpret_cast<uint2*>(dh) = uh;
        *reinterpret_cast<uint2*>(dl) = ul;
    }
}

// ---------------------------------------------------------------------------
// bf16 tensor-core GEMM (3-term split): C = (Ah+Al) @ (Bh+Bl), fp32 accum,
// fp16 output. BM=128, BK=16, 256 threads = 8 warps. Smem k-tiles stored as
// contiguous 128B 8x8 bf16 matrices -> ldmatrix.x4, conflict-free; staging
// via cp.async. (Proven in round 13: -77us.)
// ---------------------------------------------------------------------------
__device__ __forceinline__ void ldsm_x4(uint32_t r[4], uint32_t addr) {
    asm volatile("ldmatrix.sync.aligned.m8n8.x4.shared.b16 {%0,%1,%2,%3}, [%4];"
                 : "=r"(r[0]), "=r"(r[1]), "=r"(r[2]), "=r"(r[3]) : "r"(addr));
}
__device__ __forceinline__ void ldsm_x4_t(uint32_t r[4], uint32_t addr) {
    asm volatile("ldmatrix.sync.aligned.m8n8.x4.trans.shared.b16 {%0,%1,%2,%3}, [%4];"
                 : "=r"(r[0]), "=r"(r[1]), "=r"(r[2]), "=r"(r[3]) : "r"(addr));
}
__device__ __forceinline__ void mma_bf16(float c[4], const uint32_t a[4],
                                         uint32_t b0, uint32_t b1) {
    asm volatile(
        "mma.sync.aligned.m16n8k16.row.col.f32.bf16.bf16.f32 "
        "{%0,%1,%2,%3}, {%4,%5,%6,%7}, {%8,%9}, {%0,%1,%2,%3};\n"
        : "+f"(c[0]), "+f"(c[1]), "+f"(c[2]), "+f"(c[3])
        : "r"(a[0]), "r"(a[1]), "r"(a[2]), "r"(a[3]), "r"(b0), "r"(b1));
}
__device__ __forceinline__ void cp16(uint32_t dst, const void* src, int sz) {
    asm volatile("cp.async.cg.shared.global [%0], [%1], 16, %2;"
                 :: "r"(dst), "l"(src), "r"(sz));
}
#define CP_COMMIT() asm volatile("cp.async.commit_group;" ::: "memory")
#define CP_WAIT0()  asm volatile("cp.async.wait_group 0;" ::: "memory")

template <int BN, int WN>
__device__ __forceinline__ void mma_gemm_body(const __nv_bfloat16* __restrict__ Ah,
                                              const __nv_bfloat16* __restrict__ Al,
                                              const __nv_bfloat16* __restrict__ Bh,
                                              const __nv_bfloat16* __restrict__ Bl,
                                              __half* __restrict__ C,
                                              int M, int N, int K) {
    constexpr int BM  = 128;
    constexpr int NIC = BN / 8;
    constexpr int NP  = WN / 16;
    constexpr int NBLK = WN / 8;

    __shared__ uint4 sAh[2][256], sAl[2][256];
    __shared__ uint4 sBh[2][BN * 2], sBl[2][BN * 2];

    const int tid    = threadIdx.x;
    const int warpId = tid >> 5;
    const int lane   = tid & 31;
    const int row0 = blockIdx.y * BM;
    const int col0 = blockIdx.x * BN;

    const int aki = tid >> 7, ami = (tid >> 3) & 15, arow = tid & 7;
    const int aRowG = row0 + ami * 8 + arow;
    const int aDst  = (ami * 2 + aki) * 8 + arow;
    const int aszv  = (aRowG < M) ? 16 : 0;

    const bool bAct = (tid < BN * 2);
    const int bki  = tid / (NIC * 8);
    const int brem = tid % (NIC * 8);
    const int bni  = brem >> 3, brow = brem & 7;
    const int bDst = (bni * 2 + bki) * 8 + brow;
    const int bColG = col0 + bni * 8;

    uint32_t baseAh[2] = {(uint32_t)__cvta_generic_to_shared(&sAh[0][0]),
                          (uint32_t)__cvta_generic_to_shared(&sAh[1][0])};
    uint32_t baseAl[2] = {(uint32_t)__cvta_generic_to_shared(&sAl[0][0]),
                          (uint32_t)__cvta_generic_to_shared(&sAl[1][0])};
    uint32_t baseBh[2] = {(uint32_t)__cvta_generic_to_shared(&sBh[0][0]),
                          (uint32_t)__cvta_generic_to_shared(&sBh[1][0])};
    uint32_t baseBl[2] = {(uint32_t)__cvta_generic_to_shared(&sBl[0][0]),
                          (uint32_t)__cvta_generic_to_shared(&sBl[1][0])};

    auto loadTile = [&](int k0, int buf) {
        cp16(baseAh[buf] + aDst * 16, Ah + (size_t)aRowG * K + k0 + aki * 8, aszv);
        cp16(baseAl[buf] + aDst * 16, Al + (size_t)aRowG * K + k0 + aki * 8, aszv);
        if (bAct) {
            int kk = k0 + bki * 8 + brow;
            cp16(baseBh[buf] + bDst * 16, Bh + (size_t)kk * N + bColG, 16);
            cp16(baseBl[buf] + bDst * 16, Bl + (size_t)kk * N + bColG, 16);
        }
        CP_COMMIT();
    };

    const int mi0 = (warpId & 3) * 4;
    const int ni0 = (warpId >> 2) * (WN / 8);
    const int q = lane >> 3, r8 = lane & 7;
    uint32_t aoff[2], boff[NP];
#pragma unroll
    for (int mt = 0; mt < 2; mt++)
        aoff[mt] = ((mi0 + mt * 2 + (q & 1)) * 2 + (q >> 1)) * 128 + r8 * 16;
#pragma unroll
    for (int np = 0; np < NP; np++)
        boff[np] = ((ni0 + np * 2 + (q >> 1)) * 2 + (q & 1)) * 128 + r8 * 16;

    float acc[2][NBLK][4];
#pragma unroll
    for (int mt = 0; mt < 2; mt++)
#pragma unroll
        for (int nb = 0; nb < NBLK; nb++)
#pragma unroll
            for (int e = 0; e < 4; e++) acc[mt][nb][e] = 0.f;

    const int KT = K >> 4;
    loadTile(0, 0);
    int buf = 0;
    for (int t = 0; t < KT; t++) {
        CP_WAIT0();
        __syncthreads();
        if (t + 1 < KT) loadTile((t + 1) << 4, buf ^ 1);

        uint32_t ah[2][4], al[2][4];
#pragma unroll
        for (int mt = 0; mt < 2; mt++) {
            ldsm_x4(ah[mt], baseAh[buf] + aoff[mt]);
            ldsm_x4(al[mt], baseAl[buf] + aoff[mt]);
        }
#pragma unroll
        for (int np = 0; np < NP; np++) {
            uint32_t bh[4], bl[4];
            ldsm_x4_t(bh, baseBh[buf] + boff[np]);
            ldsm_x4_t(bl, baseBl[buf] + boff[np]);
#pragma unroll
            for (int mt = 0; mt < 2; mt++)
#pragma unroll
                for (int s = 0; s < 2; s++) {
                    int nb = np * 2 + s;
                    mma_bf16(acc[mt][nb], ah[mt], bh[s * 2], bh[s * 2 + 1]); // hh
                    mma_bf16(acc[mt][nb], ah[mt], bl[s * 2], bl[s * 2 + 1]); // hl
                    mma_bf16(acc[mt][nb], al[mt], bh[s * 2], bh[s * 2 + 1]); // lh
                }
        }
        __syncthreads();
        buf ^= 1;
    }

    // ---- epilogue (fp16 out): c0/c1 at (r, c..c+1), c2/c3 at (r+8, ...) ----
    const int g = lane >> 2, t4 = lane & 3;
#pragma unroll
    for (int mt = 0; mt < 2; mt++)
#pragma unroll
        for (int nb = 0; nb < NBLK; nb++) {
            int r = row0 + (warpId & 3) * 32 + mt * 16 + g;
            int c = col0 + (warpId >> 2) * WN + nb * 8 + 2 * t4;
            if (r < M)
                *reinterpret_cast<__half2*>(C + (size_t)r * N + c) =
                    __floats2half2_rn(acc[mt][nb][0], acc[mt][nb][1]);
            if (r + 8 < M)
                *reinterpret_cast<__half2*>(C + (size_t)(r + 8) * N + c) =
                    __floats2half2_rn(acc[mt][nb][2], acc[mt][nb][3]);
        }
}

__global__ void __launch_bounds__(256, 2)
sgemm1_kernel(int M, int N, int K) {
    mma_gemm_body<128, 64>(g_xh, g_xl, g_w1h, g_w1l, g_h1, M, N, K);
}

__global__ void __launch_bounds__(256, 2)
sgemm2_kernel(int M, int N, int K) {
    mma_gemm_body<64, 32>(g_x2h, g_x2l, g_w2h, g_w2l, g_h2, M, N, K);
}

// ---------------------------------------------------------------------------
// alpha_s[n,h] = <h[n,h,:], a_src[h,:]>, alpha_d likewise. One warp / node.
// hfeat is fp16 now (halved read traffic).
// ---------------------------------------------------------------------------
template <int H, int C>
__device__ __forceinline__ void alpha_body(const __half* __restrict__ hfeat,
                                           const float* __restrict__ a_src,
                                           const float* __restrict__ a_dst,
                                           float* __restrict__ as_out,
                                           float* __restrict__ ad_out, int Nn) {
    constexpr int HC  = H * C;
    constexpr int CPL = HC / 32;
    constexpr int LPH = 32 / H;
    int warp = (blockIdx.x * blockDim.x + threadIdx.x) >> 5;
    int lane = threadIdx.x & 31;
    if (warp >= Nn) return;

    const __half* hp = hfeat + (size_t)warp * HC + lane * CPL;
    float v[CPL];
    if constexpr (CPL == 8) {
        uint4 u = *reinterpret_cast<const uint4*>(hp);
        const __half2* p2 = reinterpret_cast<const __half2*>(&u);
#pragma unroll
        for (int i = 0; i < 4; i++) {
            float2 f = __half22float2(p2[i]);
            v[2 * i] = f.x; v[2 * i + 1] = f.y;
        }
    } else {
        uint32_t u = *reinterpret_cast<const uint32_t*>(hp);
        float2 f = __half22float2(*reinterpret_cast<__half2*>(&u));
        v[0] = f.x; v[1] = f.y;
    }

    float ss = 0.f, sd = 0.f;
#pragma unroll
    for (int k = 0; k < CPL; k++) {
        ss = fmaf(v[k], a_src[lane * CPL + k], ss);
        sd = fmaf(v[k], a_dst[lane * CPL + k], sd);
    }
#pragma unroll
    for (int o = LPH / 2; o > 0; o >>= 1) {
        ss += __shfl_xor_sync(0xFFFFFFFFu, ss, o);
        sd += __shfl_xor_sync(0xFFFFFFFFu, sd, o);
    }
    if ((lane % LPH) == 0) {
        int head = lane / LPH;
        as_out[warp * H + head] = ss;
        ad_out[warp * H + head] = sd;
    }
}

__global__ void alpha1_kernel(const float* __restrict__ a_src,
                              const float* __restrict__ a_dst, int Nn) {
    alpha_body<4, 64>(g_h1, a_src, a_dst, g_as1, g_ad1, Nn);
}

__global__ void alpha2_kernel(const float* __restrict__ a_src,
                              const float* __restrict__ a_dst, int Nn) {
    alpha_body<1, 64>(g_h2, a_src, a_dst, g_as2, g_ad2, Nn);
}

// ---------------------------------------------------------------------------
// SINGLE-PASS per-node softmax + weighted aggregation, fp16 gathers.
// out = (sum_e exp(e)*h[src_e]) / (sum_e exp(e) + 1e-16).
// ---------------------------------------------------------------------------
template <int H, int C, bool RELU, bool BF16OUT>
__device__ __forceinline__ void aggregate_body(const __half* __restrict__ hfeat,
                                               const float* __restrict__ as_in,
                                               const float* __restrict__ ad_in,
                                               const float* __restrict__ bias,
                                               float* __restrict__ out,
                                               __nv_bfloat16* __restrict__ outh,
                                               __nv_bfloat16* __restrict__ outl,
                                               int Nn) {
    constexpr int HC  = H * C;
    constexpr int CPL = HC / 32;     // 8 (layer1) or 2 (layer2)
    int warp = (blockIdx.x * blockDim.x + threadIdx.x) >> 5;
    int lane = threadIdx.x & 31;
    if (warp >= Nn) return;
    const int n   = warp;
    const int beg = g_rowptr[n];
    const int end = g_rowptr[n + 1];

    const int chan0 = lane * CPL;
    const int headL = chan0 / C;
    const float adh = ad_in[n * H + headL];

    auto edge_w = [&](int s) -> float {
        float e = as_in[s * H + headL] + adh;
        e = (e > 0.f) ? e : 0.2f * e;
        return expf(e);
    };

    float acc[CPL];
#pragma unroll
    for (int k = 0; k < CPL; k++) acc[k] = 0.f;
    float denom = 0.f;

    int j = beg;
    for (; j + 3 < end; j += 4) {
        int   s[4];
        float a[4];
#pragma unroll
        for (int q = 0; q < 4; q++) s[q] = g_esrc[j + q];
#pragma unroll
        for (int q = 0; q < 4; q++) { a[q] = edge_w(s[q]); denom += a[q]; }
        if constexpr (CPL == 8) {
            uint4 u[4];
#pragma unroll
            for (int q = 0; q < 4; q++)
                u[q] = *reinterpret_cast<const uint4*>(hfeat + (size_t)s[q] * HC + chan0);
#pragma unroll
            for (int q = 0; q < 4; q++) {
                const __half2* p2 = reinterpret_cast<const __half2*>(&u[q]);
#pragma unroll
                for (int i = 0; i < 4; i++) {
                    float2 f = __half22float2(p2[i]);
                    acc[2 * i]     = fmaf(f.x, a[q], acc[2 * i]);
                    acc[2 * i + 1] = fmaf(f.y, a[q], acc[2 * i + 1]);
                }
            }
        } else {
            uint32_t u[4];
#pragma unroll
            for (int q = 0; q < 4; q++)
                u[q] = *reinterpret_cast<const uint32_t*>(hfeat + (size_t)s[q] * HC + chan0);
#pragma unroll
            for (int q = 0; q < 4; q++) {
                float2 f = __half22float2(*reinterpret_cast<__half2*>(&u[q]));
                acc[0] = fmaf(f.x, a[q], acc[0]);
                acc[1] = fmaf(f.y, a[q], acc[1]);
            }
        }
    }
    for (; j < end; j++) {
        int s0 = g_esrc[j];
        float a0 = edge_w(s0);
        denom += a0;
        const __half* p0 = hfeat + (size_t)s0 * HC + chan0;
        if constexpr (CPL == 8) {
            uint4 u = *reinterpret_cast<const uint4*>(p0);
            const __half2* p2 = reinterpret_cast<const __half2*>(&u);
#pragma unroll
            for (int i = 0; i < 4; i++) {
                float2 f = __half22float2(p2[i]);
                acc[2 * i]     = fmaf(f.x, a0, acc[2 * i]);
                acc[2 * i + 1] = fmaf(f.y, a0, acc[2 * i + 1]);
            }
        } else {
            uint32_t u = *reinterpret_cast<const uint32_t*>(p0);
            float2 f = __half22float2(*reinterpret_cast<__half2*>(&u));
            acc[0] = fmaf(f.x, a0, acc[0]);
            acc[1] = fmaf(f.y, a0, acc[1]);
        }
    }

    const float inv = 1.0f / (denom + 1e-16f);
    float v[CPL];
#pragma unroll
    for (int k = 0; k < CPL; k++) {
        float w = fmaf(acc[k], inv, bias[chan0 + k]);
        if constexpr (RELU) w = fmaxf(w, 0.f);
        v[k] = w;
    }

    if constexpr (BF16OUT) {
        __nv_bfloat16 hb[CPL];
        float lof[CPL];
#pragma unroll
        for (int k = 0; k < CPL; k++) {
            hb[k] = __float2bfloat16(v[k]);
            lof[k] = v[k] - __bfloat162float(hb[k]);
        }
        uint4 uh, ul;
        {
            __nv_bfloat162 p0 = __halves2bfloat162(hb[0], hb[1]);
            __nv_bfloat162 p1 = __halves2bfloat162(hb[2], hb[3]);
            __nv_bfloat162 p2 = __halves2bfloat162(hb[4], hb[5]);
            __nv_bfloat162 p3 = __halves2bfloat162(hb[6], hb[7]);
            uh.x = *reinterpret_cast<uint32_t*>(&p0);
            uh.y = *reinterpret_cast<uint32_t*>(&p1);
            uh.z = *reinterpret_cast<uint32_t*>(&p2);
            uh.w = *reinterpret_cast<uint32_t*>(&p3);
        }
        {
            __nv_bfloat162 p0 = __floats2bfloat162_rn(lof[0], lof[1]);
            __nv_bfloat162 p1 = __floats2bfloat162_rn(lof[2], lof[3]);
            __nv_bfloat162 p2 = __floats2bfloat162_rn(lof[4], lof[5]);
            __nv_bfloat162 p3 = __floats2bfloat162_rn(lof[6], lof[7]);
            ul.x = *reinterpret_cast<uint32_t*>(&p0);
            ul.y = *reinterpret_cast<uint32_t*>(&p1);
            ul.z = *reinterpret_cast<uint32_t*>(&p2);
            ul.w = *reinterpret_cast<uint32_t*>(&p3);
        }
        *reinterpret_cast<uint4*>(outh + (size_t)n * HC + chan0) = uh;
        *reinterpret_cast<uint4*>(outl + (size_t)n * HC + chan0) = ul;
    } else {
        float* op = out + (size_t)n * HC + chan0;
#pragma unroll
        for (int k = 0; k < CPL; k++) op[k] = v[k];
    }
}

__global__ void agg1_kernel(const float* __restrict__ bias, int Nn) {
    aggregate_body<4, 64, true, true>(g_h1, g_as1, g_ad1, bias,
                                      nullptr, g_x2h, g_x2l, Nn);
}

__global__ void agg2_kernel(const float* __restrict__ bias,
                            float* __restrict__ out, int Nn) {
    aggregate_body<1, 64, false, false>(g_h2, g_as2, g_ad2, bias,
                                        out, nullptr, nullptr, Nn);
}

// ---------------------------------------------------------------------------
// kernel_launch — forked-stream DAG (proven -40us in R12):
//   main: split3 -> sgemm1 -> alpha1 -> [join CSR] agg1 -> sgemm2 -> alpha2 -> agg2
//   side: zero -> count -> scan -> fill
// ---------------------------------------------------------------------------
extern "C" void kernel_launch(void* const* d_in, const int* in_sizes, int n_in,
                              void* d_out, int out_size) {
    const float* x      = (const float*)d_in[0];
    const int*   ei     = (const int*)d_in[1];     // int32 (JAX x64 disabled)
    const float* W1     = (const float*)d_in[2];
    const float* a_src1 = (const float*)d_in[3];
    const float* a_dst1 = (const float*)d_in[4];
    const float* b1     = (const float*)d_in[5];
    const float* W2     = (const float*)d_in[6];
    const float* a_src2 = (const float*)d_in[7];
    const float* a_dst2 = (const float*)d_in[8];
    const float* b2     = (const float*)d_in[9];

    const int C   = in_sizes[9];            // 64
    const int H   = in_sizes[3] / C;        // 4
    const int HC1 = H * C;                  // 256
    const int Fin = in_sizes[2] / HC1;      // 128
    const int Nn  = in_sizes[0] / Fin;      // 50000
    const int E   = in_sizes[1] / 2;        // 800000
    const int Etot = E + Nn;

    if (Nn > NMAX || Etot > EMAX || H != 4 || C != 64 || Fin != 128) return;

    cudaStream_t s1;
    cudaStreamCreateWithFlags(&s1, cudaStreamNonBlocking);
    cudaEvent_t evFork, evCsr;
    cudaEventCreateWithFlags(&evFork, cudaEventDisableTiming);
    cudaEventCreateWithFlags(&evCsr, cudaEventDisableTiming);

    cudaEventRecord(evFork, 0);
    cudaStreamWaitEvent(s1, evFork, 0);

    // ---- CSR build on side stream ----
    zero_deg_kernel<<<(Nn + 255) / 256, 256, 0, s1>>>(Nn);
    count_kernel<<<(Etot + 255) / 256, 256, 0, s1>>>(ei, E, Nn);
    scan_kernel<<<1, 1024, 0, s1>>>(Nn);

    // ---- main stream: split + GEMM1 ----
    {
        int nx = Nn * Fin;
        int total4 = (nx + 128 * 256 + 256 * 64) >> 2;
        split3_kernel<<<(total4 + 255) / 256, 256>>>(x, W1, W2, nx);
    }
    {
        dim3 grid(HC1 / 128, (Nn + 127) / 128);
        sgemm1_kernel<<<grid, 256>>>(Nn, HC1, Fin);
    }

    fill_kernel<<<(Etot + 255) / 256, 256, 0, s1>>>(ei, E, Nn);
    cudaEventRecord(evCsr, s1);

    const int warpBlocks = (Nn + 7) / 8;
    alpha1_kernel<<<warpBlocks, 256>>>(a_src1, a_dst1, Nn);

    cudaStreamWaitEvent(0, evCsr, 0);
    agg1_kernel<<<warpBlocks, 256>>>(b1, Nn);

    // ---- layer 2 ----
    {
        dim3 grid(C / 64, (Nn + 127) / 128);
        sgemm2_kernel<<<grid, 256>>>(Nn, C, HC1);
    }
    alpha2_kernel<<<warpBlocks, 256>>>(a_src2, a_dst2, Nn);
    agg2_kernel<<<warpBlocks, 256>>>(b2, (float*)d_out, Nn);
}

// round 15
// speedup vs baseline: 2.3148x; 1.0296x over previous
#include <cuda_runtime.h>
#include <cuda_bf16.h>
#include <cuda_fp16.h>
#include <math.h>
#include <stdint.h>

// ---------------------------------------------------------------------------
// Static device scratch (no allocations allowed anywhere).
// Instance: N=50000, E=800000 (+N self loops), Fin=128, H=4, C=64.
// ---------------------------------------------------------------------------
#define NMAX 65536
#define EMAX 2200000

__device__ __half g_h1[(size_t)NMAX * 256];        // layer-1 features (fp16)
__device__ __half g_h2[(size_t)NMAX * 64];         // layer-2 features (fp16)
__device__ __nv_bfloat16 g_xh[(size_t)NMAX * 128]; // x split hi
__device__ __nv_bfloat16 g_xl[(size_t)NMAX * 128]; // x split lo
__device__ __nv_bfloat16 g_x2h[(size_t)NMAX * 256];// relu(agg1+b1) split hi
__device__ __nv_bfloat16 g_x2l[(size_t)NMAX * 256];// relu(agg1+b1) split lo
__device__ __nv_bfloat16 g_w1h[128 * 256], g_w1l[128 * 256];
__device__ __nv_bfloat16 g_w2h[256 * 64],  g_w2l[256 * 64];
__device__ float g_as1[NMAX * 4];
__device__ float g_ad1[NMAX * 4];
__device__ float g_as2[NMAX];
__device__ float g_ad2[NMAX];
__device__ int   g_deg[NMAX];
__device__ int   g_pos[NMAX];
__device__ int   g_rowptr[NMAX + 1];
__device__ int   g_esrc[EMAX];

// ---------------------------------------------------------------------------
// CSR construction (counting sort by destination). edge_index is INT32.
// ---------------------------------------------------------------------------
__global__ void zero_deg_kernel(int Nn) {
    int i = blockIdx.x * blockDim.x + threadIdx.x;
    if (i < Nn) g_deg[i] = 0;
}

__global__ void count_kernel(const int* __restrict__ ei, int E, int Nn) {
    int i = blockIdx.x * blockDim.x + threadIdx.x;
    int tot = E + Nn;
    if (i >= tot) return;
    int d = (i < E) ? ei[E + i] : (i - E);
    if ((unsigned)d < (unsigned)Nn) atomicAdd(&g_deg[d], 1);
}

__global__ void scan_kernel(int N) {
    __shared__ int ssum[1024];
    int tid = threadIdx.x;
    int chunk = (N + 1023) >> 10;
    int start = tid * chunk;
    int end = min(start + chunk, N);
    int s = 0;
    for (int i = start; i < end; i++) s += g_deg[i];
    ssum[tid] = s;
    __syncthreads();
    for (int off = 1; off < 1024; off <<= 1) {
        int v = (tid >= off) ? ssum[tid - off] : 0;
        __syncthreads();
        ssum[tid] += v;
        __syncthreads();
    }
    int run = (tid > 0) ? ssum[tid - 1] : 0;
    for (int i = start; i < end; i++) {
        g_rowptr[i] = run;
        g_pos[i] = run;
        run += g_deg[i];
    }
    if (start < N && end == N) g_rowptr[N] = run;
}

__global__ void fill_kernel(const int* __restrict__ ei, int E, int Nn) {
    int i = blockIdx.x * blockDim.x + threadIdx.x;
    int tot = E + Nn;
    if (i >= tot) return;
    int s, d;
    if (i < E) { s = ei[i]; d = ei[E + i]; }
    else       { s = d = i - E; }
    if ((unsigned)d >= (unsigned)Nn || (unsigned)s >= (unsigned)Nn) return;
    int slot = atomicAdd(&g_pos[d], 1);
    g_esrc[slot] = s;
}

// ---------------------------------------------------------------------------
// fp32 -> (bf16 hi, bf16 lo) split, vectorized: 4 floats / thread.
// ---------------------------------------------------------------------------
__global__ void split3_kernel(const float* __restrict__ x,
                              const float* __restrict__ W1,
                              const float* __restrict__ W2, int nx) {
    const int NW1 = 128 * 256, NW2 = 256 * 64;
    int total4 = (nx + NW1 + NW2) >> 2;
    for (int i = blockIdx.x * blockDim.x + threadIdx.x; i < total4;
         i += gridDim.x * blockDim.x) {
        int base = i << 2;
        const float* src;
        __nv_bfloat16 *dh, *dl;
        if (base < nx)            { src = x + base;          dh = g_xh + base;  dl = g_xl + base; }
        else if (base < nx + NW1) { int o = base - nx;       src = W1 + o; dh = g_w1h + o; dl = g_w1l + o; }
        else                      { int o = base - nx - NW1; src = W2 + o; dh = g_w2h + o; dl = g_w2l + o; }
        float4 v = *reinterpret_cast<const float4*>(src);
        __nv_bfloat16 h0 = __float2bfloat16(v.x), h1 = __float2bfloat16(v.y);
        __nv_bfloat16 h2 = __float2bfloat16(v.z), h3 = __float2bfloat16(v.w);
        __nv_bfloat162 hh0 = __halves2bfloat162(h0, h1);
        __nv_bfloat162 hh1 = __halves2bfloat162(h2, h3);
        __nv_bfloat162 ll0 = __floats2bfloat162_rn(v.x - __bfloat162float(h0),
                                                   v.y - __bfloat162float(h1));
        __nv_bfloat162 ll1 = __floats2bfloat162_rn(v.z - __bfloat162float(h2),
                                                   v.w - __bfloat162float(h3));
        uint2 uh, ul;
        uh.x = *reinterpret_cast<uint32_t*>(&hh0);
        uh.y = *reinterpret_cast<uint32_t*>(&hh1);
        ul.x = *reinterpret_cast<uint32_t*>(&ll0);
        ul.y = *reinterpret_cast<uint32_t*>(&ll1);
        *reinterpret_cast<uint2*>(dh) = uh;
        *reinterpret_cast<uint2*>(dl) = ul;
    }
}

// ---------------------------------------------------------------------------
// bf16 tensor-core GEMM (3-term split), fp16 output, with FUSED alpha
// epilogue: as[n,h] = <C_row, a_src[h,:]>, ad likewise, computed from the
// fp32 accumulators. AMODE=1 (GEMM1): each warp's WN=64 cols = exactly one
// head -> direct store, no atomics. AMODE=2 (GEMM2, H=1): two column-warps
// share each row -> combine via smem.
// ---------------------------------------------------------------------------
__device__ __forceinline__ void ldsm_x4(uint32_t r[4], uint32_t addr) {
    asm volatile("ldmatrix.sync.aligned.m8n8.x4.shared.b16 {%0,%1,%2,%3}, [%4];"
                 : "=r"(r[0]), "=r"(r[1]), "=r"(r[2]), "=r"(r[3]) : "r"(addr));
}
__device__ __forceinline__ void ldsm_x4_t(uint32_t r[4], uint32_t addr) {
    asm volatile("ldmatrix.sync.aligned.m8n8.x4.trans.shared.b16 {%0,%1,%2,%3}, [%4];"
                 : "=r"(r[0]), "=r"(r[1]), "=r"(r[2]), "=r"(r[3]) : "r"(addr));
}
__device__ __forceinline__ void mma_bf16(float c[4], const uint32_t a[4],
                                         uint32_t b0, uint32_t b1) {
    asm volatile(
        "mma.sync.aligned.m16n8k16.row.col.f32.bf16.bf16.f32 "
        "{%0,%1,%2,%3}, {%4,%5,%6,%7}, {%8,%9}, {%0,%1,%2,%3};\n"
        : "+f"(c[0]), "+f"(c[1]), "+f"(c[2]), "+f"(c[3])
        : "r"(a[0]), "r"(a[1]), "r"(a[2]), "r"(a[3]), "r"(b0), "r"(b1));
}
__device__ __forceinline__ void cp16(uint32_t dst, const void* src, int sz) {
    asm volatile("cp.async.cg.shared.global [%0], [%1], 16, %2;"
                 :: "r"(dst), "l"(src), "r"(sz));
}
#define CP_COMMIT() asm volatile("cp.async.commit_group;" ::: "memory")
#define CP_WAIT0()  asm volatile("cp.async.wait_group 0;" ::: "memory")

template <int BN, int WN, int AMODE>
__device__ __forceinline__ void mma_gemm_body(const __nv_bfloat16* __restrict__ Ah,
                                              const __nv_bfloat16* __restrict__ Al,
                                              const __nv_bfloat16* __restrict__ Bh,
                                              const __nv_bfloat16* __restrict__ Bl,
                                              __half* __restrict__ C,
                                              const float* __restrict__ asrc,
                                              const float* __restrict__ adst,
                                              float* __restrict__ as_out,
                                              float* __restrict__ ad_out,
                                              int M, int N, int K) {
    constexpr int BM  = 128;
    constexpr int NIC = BN / 8;
    constexpr int NP  = WN / 16;
    constexpr int NBLK = WN / 8;

    __shared__ uint4 sAh[2][256], sAl[2][256];
    __shared__ uint4 sBh[2][BN * 2], sBl[2][BN * 2];
    __shared__ float sAS[BM][2], sAD[BM][2];   // AMODE==2 combine buffer

    const int tid    = threadIdx.x;
    const int warpId = tid >> 5;
    const int lane   = tid & 31;
    const int row0 = blockIdx.y * BM;
    const int col0 = blockIdx.x * BN;

    const int aki = tid >> 7, ami = (tid >> 3) & 15, arow = tid & 7;
    const int aRowG = row0 + ami * 8 + arow;
    const int aDst  = (ami * 2 + aki) * 8 + arow;
    const int aszv  = (aRowG < M) ? 16 : 0;

    const bool bAct = (tid < BN * 2);
    const int bki  = tid / (NIC * 8);
    const int brem = tid % (NIC * 8);
    const int bni  = brem >> 3, brow = brem & 7;
    const int bDst = (bni * 2 + bki) * 8 + brow;
    const int bColG = col0 + bni * 8;

    uint32_t baseAh[2] = {(uint32_t)__cvta_generic_to_shared(&sAh[0][0]),
                          (uint32_t)__cvta_generic_to_shared(&sAh[1][0])};
    uint32_t baseAl[2] = {(uint32_t)__cvta_generic_to_shared(&sAl[0][0]),
                          (uint32_t)__cvta_generic_to_shared(&sAl[1][0])};
    uint32_t baseBh[2] = {(uint32_t)__cvta_generic_to_shared(&sBh[0][0]),
                          (uint32_t)__cvta_generic_to_shared(&sBh[1][0])};
    uint32_t baseBl[2] = {(uint32_t)__cvta_generic_to_shared(&sBl[0][0]),
                          (uint32_t)__cvta_generic_to_shared(&sBl[1][0])};

    auto loadTile = [&](int k0, int buf) {
        cp16(baseAh[buf] + aDst * 16, Ah + (size_t)aRowG * K + k0 + aki * 8, aszv);
        cp16(baseAl[buf] + aDst * 16, Al + (size_t)aRowG * K + k0 + aki * 8, aszv);
        if (bAct) {
            int kk = k0 + bki * 8 + brow;
            cp16(baseBh[buf] + bDst * 16, Bh + (size_t)kk * N + bColG, 16);
            cp16(baseBl[buf] + bDst * 16, Bl + (size_t)kk * N + bColG, 16);
        }
        CP_COMMIT();
    };

    const int wm = warpId & 3;
    const int wn = warpId >> 2;
    const int mi0 = wm * 4;
    const int ni0 = wn * (WN / 8);
    const int q = lane >> 3, r8 = lane & 7;
    uint32_t aoff[2], boff[NP];
#pragma unroll
    for (int mt = 0; mt < 2; mt++)
        aoff[mt] = ((mi0 + mt * 2 + (q & 1)) * 2 + (q >> 1)) * 128 + r8 * 16;
#pragma unroll
    for (int np = 0; np < NP; np++)
        boff[np] = ((ni0 + np * 2 + (q >> 1)) * 2 + (q & 1)) * 128 + r8 * 16;

    float acc[2][NBLK][4];
#pragma unroll
    for (int mt = 0; mt < 2; mt++)
#pragma unroll
        for (int nb = 0; nb < NBLK; nb++)
#pragma unroll
            for (int e = 0; e < 4; e++) acc[mt][nb][e] = 0.f;

    const int KT = K >> 4;
    loadTile(0, 0);
    int buf = 0;
    for (int t = 0; t < KT; t++) {
        CP_WAIT0();
        __syncthreads();
        if (t + 1 < KT) loadTile((t + 1) << 4, buf ^ 1);

        uint32_t ah[2][4], al[2][4];
#pragma unroll
        for (int mt = 0; mt < 2; mt++) {
            ldsm_x4(ah[mt], baseAh[buf] + aoff[mt]);
            ldsm_x4(al[mt], baseAl[buf] + aoff[mt]);
        }
#pragma unroll
        for (int np = 0; np < NP; np++) {
            uint32_t bh[4], bl[4];
            ldsm_x4_t(bh, baseBh[buf] + boff[np]);
            ldsm_x4_t(bl, baseBl[buf] + boff[np]);
#pragma unroll
            for (int mt = 0; mt < 2; mt++)
#pragma unroll
                for (int s = 0; s < 2; s++) {
                    int nb = np * 2 + s;
                    mma_bf16(acc[mt][nb], ah[mt], bh[s * 2], bh[s * 2 + 1]); // hh
                    mma_bf16(acc[mt][nb], ah[mt], bl[s * 2], bl[s * 2 + 1]); // hl
                    mma_bf16(acc[mt][nb], al[mt], bh[s * 2], bh[s * 2 + 1]); // lh
                }
        }
        __syncthreads();
        buf ^= 1;
    }

    const int g = lane >> 2, t4 = lane & 3;

    // ---- C epilogue (fp16) ----
#pragma unroll
    for (int mt = 0; mt < 2; mt++)
#pragma unroll
        for (int nb = 0; nb < NBLK; nb++) {
            int r = row0 + wm * 32 + mt * 16 + g;
            int c = col0 + wn * WN + nb * 8 + 2 * t4;
            if (r < M)
                *reinterpret_cast<__half2*>(C + (size_t)r * N + c) =
                    __floats2half2_rn(acc[mt][nb][0], acc[mt][nb][1]);
            if (r + 8 < M)
                *reinterpret_cast<__half2*>(C + (size_t)(r + 8) * N + c) =
                    __floats2half2_rn(acc[mt][nb][2], acc[mt][nb][3]);
        }

    // ---- fused alpha epilogue ----
    float a0v[NBLK], a1v[NBLK], d0v[NBLK], d1v[NBLK];
#pragma unroll
    for (int nb = 0; nb < NBLK; nb++) {
        int cw = wn * WN + nb * 8 + 2 * t4;            // col within head-span
        int cg = col0 + cw;                             // global col
        // a_src/a_dst are indexed by channel within the full HC row
        a0v[nb] = asrc[cg]; a1v[nb] = asrc[cg + 1];
        d0v[nb] = adst[cg]; d1v[nb] = adst[cg + 1];
    }
#pragma unroll
    for (int mt = 0; mt < 2; mt++) {
        float pas0 = 0.f, pad0 = 0.f, pas1 = 0.f, pad1 = 0.f;
#pragma unroll
        for (int nb = 0; nb < NBLK; nb++) {
            pas0 = fmaf(acc[mt][nb][0], a0v[nb], fmaf(acc[mt][nb][1], a1v[nb], pas0));
            pad0 = fmaf(acc[mt][nb][0], d0v[nb], fmaf(acc[mt][nb][1], d1v[nb], pad0));
            pas1 = fmaf(acc[mt][nb][2], a0v[nb], fmaf(acc[mt][nb][3], a1v[nb], pas1));
            pad1 = fmaf(acc[mt][nb][2], d0v[nb], fmaf(acc[mt][nb][3], d1v[nb], pad1));
        }
        // reduce across the 4 quad lanes (same g)
#pragma unroll
        for (int o = 1; o <= 2; o <<= 1) {
            pas0 += __shfl_xor_sync(0xFFFFFFFFu, pas0, o);
            pad0 += __shfl_xor_sync(0xFFFFFFFFu, pad0, o);
            pas1 += __shfl_xor_sync(0xFFFFFFFFu, pas1, o);
            pad1 += __shfl_xor_sync(0xFFFFFFFFu, pad1, o);
        }
        if (t4 == 0) {
            int rl = wm * 32 + mt * 16 + g;
            int r  = row0 + rl;
            if constexpr (AMODE == 1) {
                int h = (col0 >> 6) + wn;               // head owned by this warp
                if (r < M)     { as_out[r * 4 + h] = pas0; ad_out[r * 4 + h] = pad0; }
                if (r + 8 < M) { as_out[(r + 8) * 4 + h] = pas1; ad_out[(r + 8) * 4 + h] = pad1; }
            } else {
                sAS[rl][wn] = pas0;     sAD[rl][wn] = pad0;
                sAS[rl + 8][wn] = pas1; sAD[rl + 8][wn] = pad1;
            }
        }
    }
    if constexpr (AMODE == 2) {
        __syncthreads();
        for (int rl = tid; rl < BM; rl += 256) {
            int r = row0 + rl;
            if (r < M) {
                as_out[r] = sAS[rl][0] + sAS[rl][1];
                ad_out[r] = sAD[rl][0] + sAD[rl][1];
            }
        }
    }
}

__global__ void __launch_bounds__(256, 2)
sgemm1_kernel(const float* __restrict__ asrc, const float* __restrict__ adst,
              int M, int N, int K) {
    mma_gemm_body<128, 64, 1>(g_xh, g_xl, g_w1h, g_w1l, g_h1,
                              asrc, adst, g_as1, g_ad1, M, N, K);
}

__global__ void __launch_bounds__(256, 2)
sgemm2_kernel(const float* __restrict__ asrc, const float* __restrict__ adst,
              int M, int N, int K) {
    mma_gemm_body<64, 32, 2>(g_x2h, g_x2l, g_w2h, g_w2l, g_h2,
                             asrc, adst, g_as2, g_ad2, M, N, K);
}

// ---------------------------------------------------------------------------
// SINGLE-PASS per-node softmax + weighted aggregation, fp16 gathers,
// 8-edge unroll for memory-level parallelism.
// out = (sum_e exp(e)*h[src_e]) / (sum_e exp(e) + 1e-16).
// ---------------------------------------------------------------------------
template <int H, int C, bool RELU, bool BF16OUT>
__device__ __forceinline__ void aggregate_body(const __half* __restrict__ hfeat,
                                               const float* __restrict__ as_in,
                                               const float* __restrict__ ad_in,
                                               const float* __restrict__ bias,
                                               float* __restrict__ out,
                                               __nv_bfloat16* __restrict__ outh,
                                               __nv_bfloat16* __restrict__ outl,
                                               int Nn) {
    constexpr int HC  = H * C;
    constexpr int CPL = HC / 32;     // 8 (layer1) or 2 (layer2)
    int warp = (blockIdx.x * blockDim.x + threadIdx.x) >> 5;
    int lane = threadIdx.x & 31;
    if (warp >= Nn) return;
    const int n   = warp;
    const int beg = g_rowptr[n];
    const int end = g_rowptr[n + 1];

    const int chan0 = lane * CPL;
    const int headL = chan0 / C;
    const float adh = ad_in[n * H + headL];

    auto edge_w = [&](int s) -> float {
        float e = as_in[s * H + headL] + adh;
        e = (e > 0.f) ? e : 0.2f * e;
        return expf(e);
    };

    float acc[CPL];
#pragma unroll
    for (int k = 0; k < CPL; k++) acc[k] = 0.f;
    float denom = 0.f;

    int j = beg;
    // 8 edges in flight per iteration
    for (; j + 7 < end; j += 8) {
        int   s[8];
        float a[8];
#pragma unroll
        for (int q = 0; q < 8; q++) s[q] = g_esrc[j + q];
        if constexpr (CPL == 8) {
            uint4 u[8];
#pragma unroll
            for (int q = 0; q < 8; q++)
                u[q] = *reinterpret_cast<const uint4*>(hfeat + (size_t)s[q] * HC + chan0);
#pragma unroll
            for (int q = 0; q < 8; q++) { a[q] = edge_w(s[q]); denom += a[q]; }
#pragma unroll
            for (int q = 0; q < 8; q++) {
                const __half2* p2 = reinterpret_cast<const __half2*>(&u[q]);
#pragma unroll
                for (int i = 0; i < 4; i++) {
                    float2 f = __half22float2(p2[i]);
                    acc[2 * i]     = fmaf(f.x, a[q], acc[2 * i]);
                    acc[2 * i + 1] = fmaf(f.y, a[q], acc[2 * i + 1]);
                }
            }
        } else {
            uint32_t u[8];
#pragma unroll
            for (int q = 0; q < 8; q++)
                u[q] = *reinterpret_cast<const uint32_t*>(hfeat + (size_t)s[q] * HC + chan0);
#pragma unroll
            for (int q = 0; q < 8; q++) { a[q] = edge_w(s[q]); denom += a[q]; }
#pragma unroll
            for (int q = 0; q < 8; q++) {
                float2 f = __half22float2(*reinterpret_cast<__half2*>(&u[q]));
                acc[0] = fmaf(f.x, a[q], acc[0]);
                acc[1] = fmaf(f.y, a[q], acc[1]);
            }
        }
    }
    for (; j < end; j++) {
        int s0 = g_esrc[j];
        float a0 = edge_w(s0);
        denom += a0;
        const __half* p0 = hfeat + (size_t)s0 * HC + chan0;
        if constexpr (CPL == 8) {
            uint4 u = *reinterpret_cast<const uint4*>(p0);
            const __half2* p2 = reinterpret_cast<const __half2*>(&u);
#pragma unroll
            for (int i = 0; i < 4; i++) {
                float2 f = __half22float2(p2[i]);
                acc[2 * i]     = fmaf(f.x, a0, acc[2 * i]);
                acc[2 * i + 1] = fmaf(f.y, a0, acc[2 * i + 1]);
            }
        } else {
            uint32_t u = *reinterpret_cast<const uint32_t*>(p0);
            float2 f = __half22float2(*reinterpret_cast<__half2*>(&u));
            acc[0] = fmaf(f.x, a0, acc[0]);
            acc[1] = fmaf(f.y, a0, acc[1]);
        }
    }

    const float inv = 1.0f / (denom + 1e-16f);
    float v[CPL];
#pragma unroll
    for (int k = 0; k < CPL; k++) {
        float w = fmaf(acc[k], inv, bias[chan0 + k]);
        if constexpr (RELU) w = fmaxf(w, 0.f);
        v[k] = w;
    }

    if constexpr (BF16OUT) {
        __nv_bfloat16 hb[CPL];
        float lof[CPL];
#pragma unroll
        for (int k = 0; k < CPL; k++) {
            hb[k] = __float2bfloat16(v[k]);
            lof[k] = v[k] - __bfloat162float(hb[k]);
        }
        uint4 uh, ul;
        {
            __nv_bfloat162 p0 = __halves2bfloat162(hb[0], hb[1]);
            __nv_bfloat162 p1 = __halves2bfloat162(hb[2], hb[3]);
            __nv_bfloat162 p2 = __halves2bfloat162(hb[4], hb[5]);
            __nv_bfloat162 p3 = __halves2bfloat162(hb[6], hb[7]);
            uh.x = *reinterpret_cast<uint32_t*>(&p0);
            uh.y = *reinterpret_cast<uint32_t*>(&p1);
            uh.z = *reinterpret_cast<uint32_t*>(&p2);
            uh.w = *reinterpret_cast<uint32_t*>(&p3);
        }
        {
            __nv_bfloat162 p0 = __floats2bfloat162_rn(lof[0], lof[1]);
            __nv_bfloat162 p1 = __floats2bfloat162_rn(lof[2], lof[3]);
            __nv_bfloat162 p2 = __floats2bfloat162_rn(lof[4], lof[5]);
            __nv_bfloat162 p3 = __floats2bfloat162_rn(lof[6], lof[7]);
            ul.x = *reinterpret_cast<uint32_t*>(&p0);
            ul.y = *reinterpret_cast<uint32_t*>(&p1);
            ul.z = *reinterpret_cast<uint32_t*>(&p2);
            ul.w = *reinterpret_cast<uint32_t*>(&p3);
        }
        *reinterpret_cast<uint4*>(outh + (size_t)n * HC + chan0) = uh;
        *reinterpret_cast<uint4*>(outl + (size_t)n * HC + chan0) = ul;
    } else {
        float* op = out + (size_t)n * HC + chan0;
#pragma unroll
        for (int k = 0; k < CPL; k++) op[k] = v[k];
    }
}

__global__ void agg1_kernel(const float* __restrict__ bias, int Nn) {
    aggregate_body<4, 64, true, true>(g_h1, g_as1, g_ad1, bias,
                                      nullptr, g_x2h, g_x2l, Nn);
}

__global__ void agg2_kernel(const float* __restrict__ bias,
                            float* __restrict__ out, int Nn) {
    aggregate_body<1, 64, false, false>(g_h2, g_as2, g_ad2, bias,
                                        out, nullptr, nullptr, Nn);
}

// ---------------------------------------------------------------------------
// kernel_launch — forked-stream DAG:
//   main: split3 -> sgemm1(+alpha1) -> [join CSR] agg1 -> sgemm2(+alpha2) -> agg2
//   side: zero -> count -> scan -> fill
// ---------------------------------------------------------------------------
extern "C" void kernel_launch(void* const* d_in, const int* in_sizes, int n_in,
                              void* d_out, int out_size) {
    const float* x      = (const float*)d_in[0];
    const int*   ei     = (const int*)d_in[1];     // int32 (JAX x64 disabled)
    const float* W1     = (const float*)d_in[2];
    const float* a_src1 = (const float*)d_in[3];
    const float* a_dst1 = (const float*)d_in[4];
    const float* b1     = (const float*)d_in[5];
    const float* W2     = (const float*)d_in[6];
    const float* a_src2 = (const float*)d_in[7];
    const float* a_dst2 = (const float*)d_in[8];
    const float* b2     = (const float*)d_in[9];

    const int C   = in_sizes[9];            // 64
    const int H   = in_sizes[3] / C;        // 4
    const int HC1 = H * C;                  // 256
    const int Fin = in_sizes[2] / HC1;      // 128
    const int Nn  = in_sizes[0] / Fin;      // 50000
    const int E   = in_sizes[1] / 2;        // 800000
    const int Etot = E + Nn;

    if (Nn > NMAX || Etot > EMAX || H != 4 || C != 64 || Fin != 128) return;

    cudaStream_t s1;
    cudaStreamCreateWithFlags(&s1, cudaStreamNonBlocking);
    cudaEvent_t evFork, evCsr;
    cudaEventCreateWithFlags(&evFork, cudaEventDisableTiming);
    cudaEventCreateWithFlags(&evCsr, cudaEventDisableTiming);

    cudaEventRecord(evFork, 0);
    cudaStreamWaitEvent(s1, evFork, 0);

    // ---- CSR build on side stream ----
    zero_deg_kernel<<<(Nn + 255) / 256, 256, 0, s1>>>(Nn);
    count_kernel<<<(Etot + 255) / 256, 256, 0, s1>>>(ei, E, Nn);
    scan_kernel<<<1, 1024, 0, s1>>>(Nn);

    // ---- main stream: split + GEMM1 (alpha1 fused) ----
    {
        int nx = Nn * Fin;
        int total4 = (nx + 128 * 256 + 256 * 64) >> 2;
        split3_kernel<<<(total4 + 255) / 256, 256>>>(x, W1, W2, nx);
    }
    {
        dim3 grid(HC1 / 128, (Nn + 127) / 128);
        sgemm1_kernel<<<grid, 256>>>(a_src1, a_dst1, Nn, HC1, Fin);
    }

    fill_kernel<<<(Etot + 255) / 256, 256, 0, s1>>>(ei, E, Nn);
    cudaEventRecord(evCsr, s1);

    const int warpBlocks = (Nn + 7) / 8;

    // join: agg1 needs CSR + h1 + alpha1
    cudaStreamWaitEvent(0, evCsr, 0);
    agg1_kernel<<<warpBlocks, 256>>>(b1, Nn);

    // ---- layer 2 (alpha2 fused into sgemm2) ----
    {
        dim3 grid(C / 64, (Nn + 127) / 128);
        sgemm2_kernel<<<grid, 256>>>(a_src2, a_dst2, Nn, C, HC1);
    }
    agg2_kernel<<<warpBlocks, 256>>>(b2, (float*)d_out, Nn);
}